// round 10
// baseline (speedup 1.0000x reference)
#include <cuda_runtime.h>
#include <math.h>
#include <stdint.h>

// ---------------- problem constants ----------------
namespace {
constexpr int kB  = 4;
constexpr int kN  = 1024;
constexpr int kD  = 768;
constexpr int kH  = 12;
constexpr int kHD = 64;
constexpr int kGP = 49;
constexpr int kMLP = 3072;
constexpr int kT  = kB * kN;     // 4096 tokens
constexpr int kBH = kB * kH;     // 48 batched heads
constexpr int kQD = 3 * kD;      // 2304
constexpr int kGemmSmem = 3 * (128 * 20 + 16 * 136) * 4;
}

// ---------------- scratch (device globals: no allocation allowed) ----------------
__device__ float g_xn [kT * kD];
__device__ float g_qkv[kT * kQD];
__device__ float g_S  [(size_t)kBH * kN * kN];   // mixed attn A
__device__ float g_gw [kBH * kN * 64];           // softmaxed group weights, padded 49->64
__device__ float g_inv[kBH * kN];                // 1/(colsum+eps)
__device__ float g_vs [kBH * kN * kHD];          // inv-scaled V, contiguous per head
__device__ float g_ctx[kT * kD];                 // merged-head attention output
__device__ float g_y  [kT * kD];                 // after proj residual
__device__ float g_yn [kT * kD];
__device__ float g_hdn[kT * kMLP];

__device__ __forceinline__ float gelu_exact(float x) {
    return 0.5f * x * (1.0f + erff(x * 0.70710678118654752440f));
}

__device__ __forceinline__ uint32_t f2tf32(float x) {
    uint32_t r;
    asm("cvt.rna.tf32.f32 %0, %1;" : "=r"(r) : "f"(x));
    return r;
}

__device__ __forceinline__ void cp16(void* dst_smem, const void* src_gmem) {
    uint32_t d = (uint32_t)__cvta_generic_to_shared(dst_smem);
    asm volatile("cp.async.cg.shared.global [%0], [%1], 16;" :: "r"(d), "l"(src_gmem));
}
__device__ __forceinline__ void cp_commit() {
    asm volatile("cp.async.commit_group;");
}
__device__ __forceinline__ void cp_wait1() {
    asm volatile("cp.async.wait_group 1;");
}

// D += A(m16k8,row) * B(k8n8,col)   tf32
__device__ __forceinline__ void mma8(float* c, const uint32_t* a, const uint32_t* b) {
    asm volatile("mma.sync.aligned.m16n8k8.row.col.f32.tf32.tf32.f32 "
                 "{%0,%1,%2,%3}, {%4,%5,%6,%7}, {%8,%9}, {%0,%1,%2,%3};"
                 : "+f"(c[0]), "+f"(c[1]), "+f"(c[2]), "+f"(c[3])
                 : "r"(a[0]), "r"(a[1]), "r"(a[2]), "r"(a[3]),
                   "r"(b[0]), "r"(b[1]));
}

// ---------------- LayerNorm: one block (256 thr) per row of 768 ----------------
__global__ __launch_bounds__(256) void ln_kernel(const float* __restrict__ x,
                                                 const float* __restrict__ w,
                                                 const float* __restrict__ b,
                                                 float* __restrict__ out) {
    __shared__ float sh1[8], sh2[8];
    int row = blockIdx.x;
    int t = threadIdx.x;
    const float* xr = x + (size_t)row * kD;
    float v[3];
    float s = 0.f, s2 = 0.f;
#pragma unroll
    for (int i = 0; i < 3; i++) {
        v[i] = xr[t + i * 256];
        s  += v[i];
        s2 += v[i] * v[i];
    }
#pragma unroll
    for (int o = 16; o; o >>= 1) {
        s  += __shfl_xor_sync(0xffffffffu, s, o);
        s2 += __shfl_xor_sync(0xffffffffu, s2, o);
    }
    if ((t & 31) == 0) { sh1[t >> 5] = s; sh2[t >> 5] = s2; }
    __syncthreads();
    s = sh1[t & 7]; s2 = sh2[t & 7];
#pragma unroll
    for (int o = 4; o; o >>= 1) {
        s  += __shfl_xor_sync(0xffffffffu, s, o);
        s2 += __shfl_xor_sync(0xffffffffu, s2, o);
    }
    float mu   = s * (1.0f / kD);
    float var  = fmaxf(s2 * (1.0f / kD) - mu * mu, 0.f);
    float rstd = rsqrtf(var + 1e-5f);
    float* orow = out + (size_t)row * kD;
#pragma unroll
    for (int i = 0; i < 3; i++) {
        int c = t + i * 256;
        orow[c] = (v[i] - mu) * rstd * w[c] + b[c];
    }
}

// ------- TF32 dense GEMM (NN): C = A@B + bias (+gelu)(+res) -------------------
// 128x128 block, 8 warps, K-step 16, 3-stage cp.async pipeline (raw fp32 bits).
__global__ __launch_bounds__(256) void gemm_nn_tf32(
        const float* __restrict__ A, const float* __restrict__ B,
        const float* __restrict__ bias, const float* __restrict__ res,
        float* __restrict__ C, int M, int N, int K, int act) {
    extern __shared__ uint32_t dsm[];
    uint32_t* AsBuf = dsm;                      // [3][128*20]
    uint32_t* BsBuf = dsm + 3 * 128 * 20;       // [3][16*136]
#define GAS(s, r, c) AsBuf[(s) * 2560 + (r) * 20 + (c)]
#define GBS(s, r, c) BsBuf[(s) * 2176 + (r) * 136 + (c)]
    int tid = threadIdx.x, lane = tid & 31, warp = tid >> 5;
    int g = lane >> 2, tg = lane & 3;
    int wm = (warp >> 1) * 32, wn = (warp & 1) * 64;
    int row0 = blockIdx.y * 128, col0 = blockIdx.x * 128;
    int ra = tid >> 2, ca = (tid & 3) * 4;       // A loader coords
    int kb = tid >> 5, nb = (tid & 31) * 4;      // B loader coords
    const float* Abase  = A + (size_t)(row0 + ra) * K + ca;
    const float* Abase2 = A + (size_t)(row0 + ra + 64) * K + ca;
    const float* Bbase  = B + (size_t)kb * N + col0 + nb;
    const float* Bbase2 = B + (size_t)(kb + 8) * N + col0 + nb;
    float acc[2][8][4] = {};

    auto issue = [&](int k0, int s) {
        if (k0 < K) {
            cp16(&GAS(s, ra, ca),      Abase + k0);
            cp16(&GAS(s, ra + 64, ca), Abase2 + k0);
            cp16(&GBS(s, kb, nb),      Bbase + (size_t)k0 * N);
            cp16(&GBS(s, kb + 8, nb),  Bbase2 + (size_t)k0 * N);
        }
        cp_commit();
    };
    issue(0, 0);
    issue(16, 1);
    int s = 0;
    for (int k0 = 0; k0 < K; k0 += 16) {
        cp_wait1();
        __syncthreads();
        int s2n = s + 2 >= 3 ? s - 1 : s + 2;
        issue(k0 + 32, s2n);
#pragma unroll
        for (int k8 = 0; k8 < 16; k8 += 8) {
            uint32_t af[2][4], bf[8][2];
#pragma unroll
            for (int mi = 0; mi < 2; mi++) {
                int r = wm + mi * 16 + g;
                af[mi][0] = GAS(s, r, k8 + tg);
                af[mi][1] = GAS(s, r + 8, k8 + tg);
                af[mi][2] = GAS(s, r, k8 + tg + 4);
                af[mi][3] = GAS(s, r + 8, k8 + tg + 4);
            }
#pragma unroll
            for (int nj = 0; nj < 8; nj++) {
                int n = wn + nj * 8 + g;
                bf[nj][0] = GBS(s, k8 + tg, n);
                bf[nj][1] = GBS(s, k8 + tg + 4, n);
            }
#pragma unroll
            for (int mi = 0; mi < 2; mi++)
#pragma unroll
                for (int nj = 0; nj < 8; nj++)
                    mma8(acc[mi][nj], af[mi], bf[nj]);
        }
        s = s + 1 >= 3 ? 0 : s + 1;
    }
#undef GAS
#undef GBS
#pragma unroll
    for (int mi = 0; mi < 2; mi++) {
#pragma unroll
        for (int nj = 0; nj < 8; nj++) {
            int r0 = row0 + wm + mi * 16 + g;
            int c = col0 + wn + nj * 8 + tg * 2;
            float b0 = bias[c], b1 = bias[c + 1];
            float o00 = acc[mi][nj][0] + b0, o01 = acc[mi][nj][1] + b1;
            float o10 = acc[mi][nj][2] + b0, o11 = acc[mi][nj][3] + b1;
            if (act) {
                o00 = gelu_exact(o00); o01 = gelu_exact(o01);
                o10 = gelu_exact(o10); o11 = gelu_exact(o11);
            }
            if (res) {
                o00 += res[(size_t)r0 * N + c];       o01 += res[(size_t)r0 * N + c + 1];
                o10 += res[(size_t)(r0 + 8) * N + c]; o11 += res[(size_t)(r0 + 8) * N + c + 1];
            }
            *(float2*)&C[(size_t)r0 * N + c]       = make_float2(o00, o01);
            *(float2*)&C[(size_t)(r0 + 8) * N + c] = make_float2(o10, o11);
        }
    }
}

// ---- FUSED: A = (1-a)*softmax((QK^T/8) * (gw gw^T)) + a*(gw gw^T) -----------
// Block: 16 rows x 1024 cols, 64-key tiles. All smem tiles properly sized
// [.][68] (64 data cols + pad 4 => conflict-free fragment reads).
__global__ __launch_bounds__(256, 1) void sgmix_tf32(
        const float* __restrict__ qkv, const float* __restrict__ gw,
        const float* __restrict__ alpha, float* __restrict__ Aout) {
    __shared__ uint32_t Ks[64][68];
    __shared__ uint32_t Gs[64][68];
    __shared__ uint32_t Qf[16][68];
    __shared__ uint32_t Gf[16][68];
    __shared__ float red[16][8];
    int bh = blockIdx.y, b = bh / kH, h = bh % kH;
    int n0 = blockIdx.x * 16;
    const float* qb  = qkv + (size_t)b * kN * kQD + h * kHD;
    const float* kbp = qb + kD;
    const float* gwb = gw + (size_t)bh * kN * 64;
    float* Ab = Aout + (size_t)bh * kN * kN;
    int tid = threadIdx.x, lane = tid & 31, warp = tid >> 5;
    int g = lane >> 2, tg = lane & 3;
    float a_sig = 1.f / (1.f + __expf(-alpha[h]));

    // stage Q strip (scale folded, exact /8) and gw strip, RNA tf32
    {
        int r = tid >> 4, c4 = (tid & 15) * 4;
        float4 qv = *(const float4*)(qb + (size_t)(n0 + r) * kQD + c4);
        Qf[r][c4 + 0] = f2tf32(qv.x * 0.125f); Qf[r][c4 + 1] = f2tf32(qv.y * 0.125f);
        Qf[r][c4 + 2] = f2tf32(qv.z * 0.125f); Qf[r][c4 + 3] = f2tf32(qv.w * 0.125f);
        float4 gv = *(const float4*)(gwb + (size_t)(n0 + r) * 64 + c4);
        Gf[r][c4 + 0] = f2tf32(gv.x); Gf[r][c4 + 1] = f2tf32(gv.y);
        Gf[r][c4 + 2] = f2tf32(gv.z); Gf[r][c4 + 3] = f2tf32(gv.w);
    }
    __syncthreads();
    uint32_t afq[8][4], afg[8][4];
#pragma unroll
    for (int k8 = 0; k8 < 8; k8++) {
        afq[k8][0] = Qf[g][k8 * 8 + tg];
        afq[k8][1] = Qf[g + 8][k8 * 8 + tg];
        afq[k8][2] = Qf[g][k8 * 8 + tg + 4];
        afq[k8][3] = Qf[g + 8][k8 * 8 + tg + 4];
        afg[k8][0] = Gf[g][k8 * 8 + tg];
        afg[k8][1] = Gf[g + 8][k8 * 8 + tg];
        afg[k8][2] = Gf[g][k8 * 8 + tg + 4];
        afg[k8][3] = Gf[g + 8][k8 * 8 + tg + 4];
    }

    float tv_[16][4];    // t = S*G, later e = exp(t - mx)
    float gv_[16][4];    // G values (kept for the a*G mix)
    for (int ct = 0; ct < 16; ct++) {
        int m0 = ct * 64;
        __syncthreads();
#pragma unroll
        for (int i = 0; i < 4; i++) {
            int idx = tid + i * 256;          // 1024 float4 slots: 64 rows x 16
            int r = idx >> 4, c4 = (idx & 15) * 4;
            float4 kv = *(const float4*)(kbp + (size_t)(m0 + r) * kQD + c4);
            Ks[r][c4 + 0] = f2tf32(kv.x); Ks[r][c4 + 1] = f2tf32(kv.y);
            Ks[r][c4 + 2] = f2tf32(kv.z); Ks[r][c4 + 3] = f2tf32(kv.w);
            float4 gg = *(const float4*)(gwb + (size_t)(m0 + r) * 64 + c4);
            Gs[r][c4 + 0] = f2tf32(gg.x); Gs[r][c4 + 1] = f2tf32(gg.y);
            Gs[r][c4 + 2] = f2tf32(gg.z); Gs[r][c4 + 3] = f2tf32(gg.w);
        }
        __syncthreads();
        float sacc[4] = {}, gacc[4] = {};
        int n = warp * 8 + g;
#pragma unroll
        for (int k8 = 0; k8 < 8; k8++) {
            uint32_t bfk[2] = { Ks[n][k8 * 8 + tg], Ks[n][k8 * 8 + tg + 4] };
            uint32_t bfg[2] = { Gs[n][k8 * 8 + tg], Gs[n][k8 * 8 + tg + 4] };
            mma8(sacc, afq[k8], bfk);
            mma8(gacc, afg[k8], bfg);
        }
#pragma unroll
        for (int i = 0; i < 4; i++) {
            gv_[ct][i] = gacc[i];
            tv_[ct][i] = sacc[i] * gacc[i];
        }
    }

    // per-row maxima (rows n0+g and n0+g+8)
    float mx0 = -1e30f, mx1 = -1e30f;
#pragma unroll
    for (int ct = 0; ct < 16; ct++) {
        mx0 = fmaxf(mx0, fmaxf(tv_[ct][0], tv_[ct][1]));
        mx1 = fmaxf(mx1, fmaxf(tv_[ct][2], tv_[ct][3]));
    }
    mx0 = fmaxf(mx0, __shfl_xor_sync(0xffffffffu, mx0, 1));
    mx0 = fmaxf(mx0, __shfl_xor_sync(0xffffffffu, mx0, 2));
    mx1 = fmaxf(mx1, __shfl_xor_sync(0xffffffffu, mx1, 1));
    mx1 = fmaxf(mx1, __shfl_xor_sync(0xffffffffu, mx1, 2));
    __syncthreads();
    if (tg == 0) { red[g][warp] = mx0; red[g + 8][warp] = mx1; }
    __syncthreads();
    mx0 = red[g][0]; mx1 = red[g + 8][0];
#pragma unroll
    for (int w = 1; w < 8; w++) {
        mx0 = fmaxf(mx0, red[g][w]);
        mx1 = fmaxf(mx1, red[g + 8][w]);
    }
    __syncthreads();
    // exp + row sums
    float sum0 = 0.f, sum1 = 0.f;
#pragma unroll
    for (int ct = 0; ct < 16; ct++) {
        tv_[ct][0] = __expf(tv_[ct][0] - mx0);
        tv_[ct][1] = __expf(tv_[ct][1] - mx0);
        tv_[ct][2] = __expf(tv_[ct][2] - mx1);
        tv_[ct][3] = __expf(tv_[ct][3] - mx1);
        sum0 += tv_[ct][0] + tv_[ct][1];
        sum1 += tv_[ct][2] + tv_[ct][3];
    }
    sum0 += __shfl_xor_sync(0xffffffffu, sum0, 1);
    sum0 += __shfl_xor_sync(0xffffffffu, sum0, 2);
    sum1 += __shfl_xor_sync(0xffffffffu, sum1, 1);
    sum1 += __shfl_xor_sync(0xffffffffu, sum1, 2);
    if (tg == 0) { red[g][warp] = sum0; red[g + 8][warp] = sum1; }
    __syncthreads();
    sum0 = 0.f; sum1 = 0.f;
#pragma unroll
    for (int w = 0; w < 8; w++) { sum0 += red[g][w]; sum1 += red[g + 8][w]; }
    float is0 = (1.f - a_sig) / sum0;
    float is1 = (1.f - a_sig) / sum1;
    // mix and store A
#pragma unroll
    for (int ct = 0; ct < 16; ct++) {
        int c = ct * 64 + warp * 8 + tg * 2;
        float2 o0 = make_float2(tv_[ct][0] * is0 + a_sig * gv_[ct][0],
                                tv_[ct][1] * is0 + a_sig * gv_[ct][1]);
        float2 o1 = make_float2(tv_[ct][2] * is1 + a_sig * gv_[ct][2],
                                tv_[ct][3] * is1 + a_sig * gv_[ct][3]);
        *(float2*)&Ab[(size_t)(n0 + g) * kN + c] = o0;
        *(float2*)&Ab[(size_t)(n0 + g + 8) * kN + c] = o1;
    }
}

// ------- vs[bh][k][d] = V[b,k,h,d] * inv[bh,k]  (contiguous per head) --------
__global__ __launch_bounds__(256) void vscale_kernel(const float* __restrict__ qkv,
                                                     const float* __restrict__ inv,
                                                     float* __restrict__ vs) {
    int idx = blockIdx.x * 256 + threadIdx.x;       // over kBH*kN*16 float4s
    int d4 = (idx & 15) * 4;
    int k  = (idx >> 4) & 1023;
    int bh = idx >> 14;
    int b = bh / kH, h = bh % kH;
    float iv = inv[bh * kN + k];
    float4 v = *(const float4*)(qkv + (size_t)(b * kN + k) * kQD + 2 * kD + h * kHD + d4);
    v.x *= iv; v.y *= iv; v.z *= iv; v.w *= iv;
    *(float4*)(vs + (size_t)bh * kN * kHD + (size_t)k * kHD + d4) = v;
}

// ------- out = A @ Vs (NN), tf32, 3-stage cp.async; heads merged into ctx -----
__global__ __launch_bounds__(256) void av_tf32(const float* __restrict__ Sa,
                                               const float* __restrict__ vs,
                                               float* __restrict__ ctx) {
    __shared__ __align__(16) uint32_t As[3][128][20];
    __shared__ __align__(16) uint32_t Bs[3][16][72];
    int bh = blockIdx.z, b = bh / kH, h = bh % kH;
    const float* Ab = Sa + (size_t)bh * kN * kN;
    const float* vb = vs + (size_t)bh * kN * kHD;
    int tid = threadIdx.x, lane = tid & 31, warp = tid >> 5;
    int g = lane >> 2, tg = lane & 3;
    int wm = (warp >> 1) * 32, wn = (warp & 1) * 32;
    int row0 = blockIdx.y * 128;
    int ra = tid >> 2, ca = (tid & 3) * 4;
    int kr = tid >> 4, nc = (tid & 15) * 4;
    const float* Ap0 = Ab + (size_t)(row0 + ra) * kN + ca;
    const float* Ap1 = Ap0 + (size_t)64 * kN;
    const float* Vp  = vb + (size_t)kr * kHD + nc;
    float acc[2][4][4] = {};
    auto issue = [&](int k0, int s) {
        if (k0 < kN) {
            cp16(&As[s][ra][ca],      Ap0 + k0);
            cp16(&As[s][ra + 64][ca], Ap1 + k0);
            cp16(&Bs[s][kr][nc],      Vp + (size_t)k0 * kHD);
        }
        cp_commit();
    };
    issue(0, 0);
    issue(16, 1);
    int s = 0;
    for (int k0 = 0; k0 < kN; k0 += 16) {
        cp_wait1();
        __syncthreads();
        int s2n = s + 2 >= 3 ? s - 1 : s + 2;
        issue(k0 + 32, s2n);
#pragma unroll
        for (int k8 = 0; k8 < 16; k8 += 8) {
            uint32_t af[2][4], bf[4][2];
#pragma unroll
            for (int mi = 0; mi < 2; mi++) {
                int r = wm + mi * 16 + g;
                af[mi][0] = As[s][r][k8 + tg];
                af[mi][1] = As[s][r + 8][k8 + tg];
                af[mi][2] = As[s][r][k8 + tg + 4];
                af[mi][3] = As[s][r + 8][k8 + tg + 4];
            }
#pragma unroll
            for (int nj = 0; nj < 4; nj++) {
                int n = wn + nj * 8 + g;
                bf[nj][0] = Bs[s][k8 + tg][n];
                bf[nj][1] = Bs[s][k8 + tg + 4][n];
            }
#pragma unroll
            for (int mi = 0; mi < 2; mi++)
#pragma unroll
                for (int nj = 0; nj < 4; nj++)
                    mma8(acc[mi][nj], af[mi], bf[nj]);
        }
        s = s + 1 >= 3 ? 0 : s + 1;
    }
#pragma unroll
    for (int mi = 0; mi < 2; mi++) {
#pragma unroll
        for (int nj = 0; nj < 4; nj++) {
            int tok0 = b * kN + row0 + wm + mi * 16 + g;
            int c = h * kHD + wn + nj * 8 + tg * 2;
            *(float2*)&ctx[(size_t)tok0 * kD + c] =
                make_float2(acc[mi][nj][0], acc[mi][nj][1]);
            *(float2*)&ctx[(size_t)(tok0 + 8) * kD + c] =
                make_float2(acc[mi][nj][2], acc[mi][nj][3]);
        }
    }
}

// ---- group weights: gw = softmax(gelu(V @ gp^T)) padded to 64 ----
__global__ __launch_bounds__(256) void gw_kernel(const float* __restrict__ qkv,
                                                 const float* __restrict__ gp_w,
                                                 float* __restrict__ gw) {
    __shared__ __align__(16) float gps[kGP][68];
    __shared__ __align__(16) float Vs[64][68];
    int bh = blockIdx.y;
    int b = bh / kH, h = bh % kH;
    int n0 = blockIdx.x * 64;
    int tid = threadIdx.x;
    const float* gph = gp_w + (size_t)h * kGP * kHD;
    for (int i = tid; i < kGP * 16; i += 256) {
        int r = i >> 4, c4 = (i & 15) * 4;
        *(float4*)&gps[r][c4] = *(const float4*)(gph + r * kHD + c4);
    }
    const float* vb = qkv + (size_t)(b * kN + n0) * kQD + 2 * kD + h * kHD;
    for (int i = tid; i < 64 * 16; i += 256) {
        int r = i >> 4, c4 = (i & 15) * 4;
        *(float4*)&Vs[r][c4] = *(const float4*)(vb + (size_t)r * kQD + c4);
    }
    __syncthreads();
    int r = tid >> 2;
    int c0 = tid & 3;
    float val[13];
    float mx = -1e30f;
#pragma unroll
    for (int j = 0; j < 13; j++) {
        int c = c0 + 4 * j;
        float acc = 0.f;
        if (c < kGP) {
#pragma unroll
            for (int d = 0; d < kHD; d += 4) {
                float4 vv = *(const float4*)&Vs[r][d];
                float4 gg = *(const float4*)&gps[c][d];
                acc += vv.x * gg.x + vv.y * gg.y + vv.z * gg.z + vv.w * gg.w;
            }
            acc = gelu_exact(acc);
            mx = fmaxf(mx, acc);
        }
        val[j] = acc;
    }
    mx = fmaxf(mx, __shfl_xor_sync(0xffffffffu, mx, 1));
    mx = fmaxf(mx, __shfl_xor_sync(0xffffffffu, mx, 2));
    float sum = 0.f;
#pragma unroll
    for (int j = 0; j < 13; j++) {
        int c = c0 + 4 * j;
        val[j] = (c < kGP) ? __expf(val[j] - mx) : 0.f;
        sum += val[j];
    }
    sum += __shfl_xor_sync(0xffffffffu, sum, 1);
    sum += __shfl_xor_sync(0xffffffffu, sum, 2);
    float is = 1.f / sum;
    float* grow = gw + (size_t)(bh * kN + n0 + r) * 64;
#pragma unroll
    for (int j = 0; j < 16; j++) {
        int c = c0 + 4 * j;
        if (c < 64) grow[c] = (j < 13 && c < kGP) ? val[j] * is : 0.f;
    }
}

// ------- column sums over n (axis=2), stores 1/(sum+1e-8) -------
__global__ __launch_bounds__(256) void colsum_kernel(const float* __restrict__ Sa,
                                                     float* __restrict__ inv) {
    int idx = blockIdx.x * 256 + threadIdx.x;   // bh*N + m
    int bh = idx >> 10, m = idx & 1023;
    const float* p = Sa + (size_t)bh * kN * kN + m;
    float s0 = 0.f, s1 = 0.f, s2 = 0.f, s3 = 0.f;
    float s4 = 0.f, s5 = 0.f, s6 = 0.f, s7 = 0.f;
#pragma unroll 4
    for (int n = 0; n < kN; n += 8) {
        s0 += p[(size_t)(n + 0) * kN];
        s1 += p[(size_t)(n + 1) * kN];
        s2 += p[(size_t)(n + 2) * kN];
        s3 += p[(size_t)(n + 3) * kN];
        s4 += p[(size_t)(n + 4) * kN];
        s5 += p[(size_t)(n + 5) * kN];
        s6 += p[(size_t)(n + 6) * kN];
        s7 += p[(size_t)(n + 7) * kN];
    }
    float s = ((s0 + s1) + (s2 + s3)) + ((s4 + s5) + (s6 + s7));
    inv[idx] = 1.f / (s + 1e-8f);
}

// ---------------- launch ----------------
extern "C" void kernel_launch(void* const* d_in, const int* in_sizes, int n_in,
                              void* d_out, int out_size) {
    const float* x      = (const float*)d_in[0];
    const float* ln1_w  = (const float*)d_in[1];
    const float* ln1_b  = (const float*)d_in[2];
    const float* qkv_w  = (const float*)d_in[3];
    const float* qkv_b  = (const float*)d_in[4];
    const float* proj_w = (const float*)d_in[5];
    const float* proj_b = (const float*)d_in[6];
    const float* gp_w   = (const float*)d_in[7];
    const float* alpha  = (const float*)d_in[8];
    const float* ln2_w  = (const float*)d_in[9];
    const float* ln2_b  = (const float*)d_in[10];
    const float* ff1_w  = (const float*)d_in[11];
    const float* ff1_b  = (const float*)d_in[12];
    const float* ff2_w  = (const float*)d_in[13];
    const float* ff2_b  = (const float*)d_in[14];
    float* out = (float*)d_out;

    float *xn, *qkv, *S, *gw, *inv, *vs, *ctx, *y, *yn, *hdn;
    cudaGetSymbolAddress((void**)&xn,  g_xn);
    cudaGetSymbolAddress((void**)&qkv, g_qkv);
    cudaGetSymbolAddress((void**)&S,   g_S);
    cudaGetSymbolAddress((void**)&gw,  g_gw);
    cudaGetSymbolAddress((void**)&inv, g_inv);
    cudaGetSymbolAddress((void**)&vs,  g_vs);
    cudaGetSymbolAddress((void**)&ctx, g_ctx);
    cudaGetSymbolAddress((void**)&y,   g_y);
    cudaGetSymbolAddress((void**)&yn,  g_yn);
    cudaGetSymbolAddress((void**)&hdn, g_hdn);

    cudaFuncSetAttribute(gemm_nn_tf32,
                         cudaFuncAttributeMaxDynamicSharedMemorySize, kGemmSmem);

    // attention branch
    ln_kernel<<<kT, 256>>>(x, ln1_w, ln1_b, xn);
    gemm_nn_tf32<<<dim3(kQD / 128, kT / 128), 256, kGemmSmem>>>(
        xn, qkv_w, qkv_b, nullptr, qkv, kT, kQD, kD, 0);
    gw_kernel<<<dim3(kN / 64, kBH), 256>>>(qkv, gp_w, gw);
    sgmix_tf32<<<dim3(kN / 16, kBH), 256>>>(qkv, gw, alpha, S);
    colsum_kernel<<<kBH * kN / 256, 256>>>(S, inv);
    vscale_kernel<<<kBH * kN * 16 / 256, 256>>>(qkv, inv, vs);
    av_tf32<<<dim3(1, 8, kBH), 256>>>(S, vs, ctx);
    gemm_nn_tf32<<<dim3(kD / 128, kT / 128), 256, kGemmSmem>>>(
        ctx, proj_w, proj_b, x, y, kT, kD, kD, 0);
    // FFN branch
    ln_kernel<<<kT, 256>>>(y, ln2_w, ln2_b, yn);
    gemm_nn_tf32<<<dim3(kMLP / 128, kT / 128), 256, kGemmSmem>>>(
        yn, ff1_w, ff1_b, nullptr, hdn, kT, kMLP, kD, 1);
    gemm_nn_tf32<<<dim3(kD / 128, kT / 128), 256, kGemmSmem>>>(
        hdn, ff2_w, ff2_b, y, out, kT, kD, kMLP, 0);
}

// round 11
// speedup vs baseline: 1.1877x; 1.1877x over previous
#include <cuda_runtime.h>
#include <math.h>
#include <stdint.h>

// ---------------- problem constants ----------------
namespace {
constexpr int kB  = 4;
constexpr int kN  = 1024;
constexpr int kD  = 768;
constexpr int kH  = 12;
constexpr int kHD = 64;
constexpr int kGP = 49;
constexpr int kMLP = 3072;
constexpr int kT  = kB * kN;     // 4096 tokens
constexpr int kBH = kB * kH;     // 48 batched heads
constexpr int kQD = 3 * kD;      // 2304
// gemm dynamic smem: 4 stages of (As 128x20 + Bs 16x136) uint32
constexpr int kGemmSmem = 4 * (128 * 20 + 16 * 136) * 4;
}

// ---------------- scratch (device globals: no allocation allowed) ----------------
__device__ float g_xn [kT * kD];
__device__ float g_qkv[kT * kQD];
__device__ float g_S  [(size_t)kBH * kN * kN];   // scores, later the mixed attn A
__device__ float g_G  [(size_t)kBH * kN * kN];   // gw @ gw^T
__device__ float g_gw [kBH * kN * 64];           // softmaxed group weights, padded 49->64
__device__ float g_inv[kBH * kN];                // 1/(colsum+eps)
__device__ float g_vs [kBH * kN * kHD];          // inv-scaled V, contiguous per head
__device__ float g_ctx[kT * kD];                 // merged-head attention output
__device__ float g_y  [kT * kD];                 // after proj residual
__device__ float g_yn [kT * kD];
__device__ float g_hdn[kT * kMLP];

__device__ __forceinline__ float gelu_exact(float x) {
    return 0.5f * x * (1.0f + erff(x * 0.70710678118654752440f));
}

__device__ __forceinline__ uint32_t f2tf32(float x) {
    uint32_t r;
    asm("cvt.rna.tf32.f32 %0, %1;" : "=r"(r) : "f"(x));
    return r;
}

__device__ __forceinline__ void cp16(void* dst_smem, const void* src_gmem) {
    uint32_t d = (uint32_t)__cvta_generic_to_shared(dst_smem);
    asm volatile("cp.async.cg.shared.global [%0], [%1], 16;" :: "r"(d), "l"(src_gmem));
}
__device__ __forceinline__ void cp_commit() {
    asm volatile("cp.async.commit_group;");
}
__device__ __forceinline__ void cp_wait1() {
    asm volatile("cp.async.wait_group 1;");
}
__device__ __forceinline__ void cp_wait2() {
    asm volatile("cp.async.wait_group 2;");
}

// D += A(m16k8,row) * B(k8n8,col)   tf32
__device__ __forceinline__ void mma8(float* c, const uint32_t* a, const uint32_t* b) {
    asm volatile("mma.sync.aligned.m16n8k8.row.col.f32.tf32.tf32.f32 "
                 "{%0,%1,%2,%3}, {%4,%5,%6,%7}, {%8,%9}, {%0,%1,%2,%3};"
                 : "+f"(c[0]), "+f"(c[1]), "+f"(c[2]), "+f"(c[3])
                 : "r"(a[0]), "r"(a[1]), "r"(a[2]), "r"(a[3]),
                   "r"(b[0]), "r"(b[1]));
}

// ---------------- LayerNorm: one block (256 thr) per row of 768 ----------------
__global__ __launch_bounds__(256) void ln_kernel(const float* __restrict__ x,
                                                 const float* __restrict__ w,
                                                 const float* __restrict__ b,
                                                 float* __restrict__ out) {
    __shared__ float sh1[8], sh2[8];
    int row = blockIdx.x;
    int t = threadIdx.x;
    const float* xr = x + (size_t)row * kD;
    float v[3];
    float s = 0.f, s2 = 0.f;
#pragma unroll
    for (int i = 0; i < 3; i++) {
        v[i] = xr[t + i * 256];
        s  += v[i];
        s2 += v[i] * v[i];
    }
#pragma unroll
    for (int o = 16; o; o >>= 1) {
        s  += __shfl_xor_sync(0xffffffffu, s, o);
        s2 += __shfl_xor_sync(0xffffffffu, s2, o);
    }
    if ((t & 31) == 0) { sh1[t >> 5] = s; sh2[t >> 5] = s2; }
    __syncthreads();
    s = sh1[t & 7]; s2 = sh2[t & 7];
#pragma unroll
    for (int o = 4; o; o >>= 1) {
        s  += __shfl_xor_sync(0xffffffffu, s, o);
        s2 += __shfl_xor_sync(0xffffffffu, s2, o);
    }
    float mu   = s * (1.0f / kD);
    float var  = fmaxf(s2 * (1.0f / kD) - mu * mu, 0.f);
    float rstd = rsqrtf(var + 1e-5f);
    float* orow = out + (size_t)row * kD;
#pragma unroll
    for (int i = 0; i < 3; i++) {
        int c = t + i * 256;
        orow[c] = (v[i] - mu) * rstd * w[c] + b[c];
    }
}

// ------- TF32 dense GEMM (NN): C = A@B + bias (+gelu)(+res) -------------------
// 128x128 block, 8 warps, K-step 16, 4-stage cp.async pipeline (raw fp32 bits).
__global__ __launch_bounds__(256) void gemm_nn_tf32(
        const float* __restrict__ A, const float* __restrict__ B,
        const float* __restrict__ bias, const float* __restrict__ res,
        float* __restrict__ C, int M, int N, int K, int act) {
    extern __shared__ uint32_t dsm[];
    uint32_t* AsBuf = dsm;                      // [4][128*20]
    uint32_t* BsBuf = dsm + 4 * 128 * 20;       // [4][16*136]
#define GAS(s, r, c) AsBuf[(s) * 2560 + (r) * 20 + (c)]
#define GBS(s, r, c) BsBuf[(s) * 2176 + (r) * 136 + (c)]
    int tid = threadIdx.x, lane = tid & 31, warp = tid >> 5;
    int g = lane >> 2, tg = lane & 3;
    int wm = (warp >> 1) * 32, wn = (warp & 1) * 64;
    int row0 = blockIdx.y * 128, col0 = blockIdx.x * 128;
    int ra = tid >> 2, ca = (tid & 3) * 4;       // A loader coords
    int kb = tid >> 5, nb = (tid & 31) * 4;      // B loader coords
    const float* Abase  = A + (size_t)(row0 + ra) * K + ca;
    const float* Abase2 = A + (size_t)(row0 + ra + 64) * K + ca;
    const float* Bbase  = B + (size_t)kb * N + col0 + nb;
    const float* Bbase2 = B + (size_t)(kb + 8) * N + col0 + nb;
    float acc[2][8][4] = {};

    auto issue = [&](int k0, int s) {
        if (k0 < K) {
            cp16(&GAS(s, ra, ca),      Abase + k0);
            cp16(&GAS(s, ra + 64, ca), Abase2 + k0);
            cp16(&GBS(s, kb, nb),      Bbase + (size_t)k0 * N);
            cp16(&GBS(s, kb + 8, nb),  Bbase2 + (size_t)k0 * N);
        }
        cp_commit();
    };
    issue(0, 0);
    issue(16, 1);
    issue(32, 2);
    int s = 0;
    for (int k0 = 0; k0 < K; k0 += 16) {
        cp_wait2();
        __syncthreads();
        issue(k0 + 48, (s + 3) & 3);
#pragma unroll
        for (int k8 = 0; k8 < 16; k8 += 8) {
            uint32_t af[2][4], bf[8][2];
#pragma unroll
            for (int mi = 0; mi < 2; mi++) {
                int r = wm + mi * 16 + g;
                af[mi][0] = GAS(s, r, k8 + tg);
                af[mi][1] = GAS(s, r + 8, k8 + tg);
                af[mi][2] = GAS(s, r, k8 + tg + 4);
                af[mi][3] = GAS(s, r + 8, k8 + tg + 4);
            }
#pragma unroll
            for (int nj = 0; nj < 8; nj++) {
                int n = wn + nj * 8 + g;
                bf[nj][0] = GBS(s, k8 + tg, n);
                bf[nj][1] = GBS(s, k8 + tg + 4, n);
            }
#pragma unroll
            for (int mi = 0; mi < 2; mi++)
#pragma unroll
                for (int nj = 0; nj < 8; nj++)
                    mma8(acc[mi][nj], af[mi], bf[nj]);
        }
        s = (s + 1) & 3;
    }
#undef GAS
#undef GBS
#pragma unroll
    for (int mi = 0; mi < 2; mi++) {
#pragma unroll
        for (int nj = 0; nj < 8; nj++) {
            int r0 = row0 + wm + mi * 16 + g;
            int c = col0 + wn + nj * 8 + tg * 2;
            float b0 = bias[c], b1 = bias[c + 1];
            float o00 = acc[mi][nj][0] + b0, o01 = acc[mi][nj][1] + b1;
            float o10 = acc[mi][nj][2] + b0, o11 = acc[mi][nj][3] + b1;
            if (act) {
                o00 = gelu_exact(o00); o01 = gelu_exact(o01);
                o10 = gelu_exact(o10); o11 = gelu_exact(o11);
            }
            if (res) {
                o00 += res[(size_t)r0 * N + c];       o01 += res[(size_t)r0 * N + c + 1];
                o10 += res[(size_t)(r0 + 8) * N + c]; o11 += res[(size_t)(r0 + 8) * N + c + 1];
            }
            *(float2*)&C[(size_t)r0 * N + c]       = make_float2(o00, o01);
            *(float2*)&C[(size_t)(r0 + 8) * N + c] = make_float2(o10, o11);
        }
    }
}

// ---------------- scores S = scale * Q @ K^T (NT), tf32, batched over BH ------
__global__ __launch_bounds__(256) void score_tf32(const float* __restrict__ qkv,
                                                  float* __restrict__ S) {
    __shared__ uint32_t As[128][20];
    __shared__ uint32_t Bs[128][20];
    int bh = blockIdx.z, b = bh / kH, h = bh % kH;
    const float* qb = qkv + (size_t)b * kN * kQD + h * kHD;
    const float* kb = qb + kD;
    int tid = threadIdx.x, lane = tid & 31, warp = tid >> 5;
    int g = lane >> 2, tg = lane & 3;
    int wm = (warp >> 1) * 32, wn = (warp & 1) * 64;
    int n0 = blockIdx.y * 128, m0 = blockIdx.x * 128;
    int ra = tid >> 2, ca = (tid & 3) * 4;
    const float* Qp0 = qb + (size_t)(n0 + ra) * kQD + ca;
    const float* Qp1 = Qp0 + (size_t)64 * kQD;
    const float* Kp0 = kb + (size_t)(m0 + ra) * kQD + ca;
    const float* Kp1 = Kp0 + (size_t)64 * kQD;
    float acc[2][8][4] = {};
    float4 q0 = *(const float4*)Qp0, q1 = *(const float4*)Qp1;
    float4 v0 = *(const float4*)Kp0, v1 = *(const float4*)Kp1;
    for (int k0 = 0; k0 < kHD; k0 += 16) {
        As[ra][ca + 0] = f2tf32(q0.x); As[ra][ca + 1] = f2tf32(q0.y);
        As[ra][ca + 2] = f2tf32(q0.z); As[ra][ca + 3] = f2tf32(q0.w);
        As[ra + 64][ca + 0] = f2tf32(q1.x); As[ra + 64][ca + 1] = f2tf32(q1.y);
        As[ra + 64][ca + 2] = f2tf32(q1.z); As[ra + 64][ca + 3] = f2tf32(q1.w);
        Bs[ra][ca + 0] = f2tf32(v0.x); Bs[ra][ca + 1] = f2tf32(v0.y);
        Bs[ra][ca + 2] = f2tf32(v0.z); Bs[ra][ca + 3] = f2tf32(v0.w);
        Bs[ra + 64][ca + 0] = f2tf32(v1.x); Bs[ra + 64][ca + 1] = f2tf32(v1.y);
        Bs[ra + 64][ca + 2] = f2tf32(v1.z); Bs[ra + 64][ca + 3] = f2tf32(v1.w);
        __syncthreads();
        if (k0 + 16 < kHD) {
            q0 = *(const float4*)(Qp0 + k0 + 16);
            q1 = *(const float4*)(Qp1 + k0 + 16);
            v0 = *(const float4*)(Kp0 + k0 + 16);
            v1 = *(const float4*)(Kp1 + k0 + 16);
        }
#pragma unroll
        for (int k8 = 0; k8 < 16; k8 += 8) {
            uint32_t af[2][4], bf[8][2];
#pragma unroll
            for (int mi = 0; mi < 2; mi++) {
                int r = wm + mi * 16 + g;
                af[mi][0] = As[r][k8 + tg];
                af[mi][1] = As[r + 8][k8 + tg];
                af[mi][2] = As[r][k8 + tg + 4];
                af[mi][3] = As[r + 8][k8 + tg + 4];
            }
#pragma unroll
            for (int nj = 0; nj < 8; nj++) {
                int n = wn + nj * 8 + g;
                bf[nj][0] = Bs[n][k8 + tg];
                bf[nj][1] = Bs[n][k8 + tg + 4];
            }
#pragma unroll
            for (int mi = 0; mi < 2; mi++)
#pragma unroll
                for (int nj = 0; nj < 8; nj++)
                    mma8(acc[mi][nj], af[mi], bf[nj]);
        }
        __syncthreads();
    }
    float* Sb = S + (size_t)bh * kN * kN;
#pragma unroll
    for (int mi = 0; mi < 2; mi++) {
#pragma unroll
        for (int nj = 0; nj < 8; nj++) {
            int r0 = n0 + wm + mi * 16 + g;
            int c = m0 + wn + nj * 8 + tg * 2;
            *(float2*)&Sb[(size_t)r0 * kN + c] =
                make_float2(acc[mi][nj][0] * 0.125f, acc[mi][nj][1] * 0.125f);
            *(float2*)&Sb[(size_t)(r0 + 8) * kN + c] =
                make_float2(acc[mi][nj][2] * 0.125f, acc[mi][nj][3] * 0.125f);
        }
    }
}

// ---------------- G = gw @ gw^T (NT), tf32, K=64 padded ----------------
__global__ __launch_bounds__(256) void gmat_tf32(const float* __restrict__ gw,
                                                 float* __restrict__ G) {
    __shared__ uint32_t As[128][20];
    __shared__ uint32_t Bs[128][20];
    int bh = blockIdx.z;
    const float* gb = gw + (size_t)bh * kN * 64;
    int tid = threadIdx.x, lane = tid & 31, warp = tid >> 5;
    int g = lane >> 2, tg = lane & 3;
    int wm = (warp >> 1) * 32, wn = (warp & 1) * 64;
    int n0 = blockIdx.y * 128, m0 = blockIdx.x * 128;
    int ra = tid >> 2, ca = (tid & 3) * 4;
    const float* Ap0 = gb + (size_t)(n0 + ra) * 64 + ca;
    const float* Ap1 = Ap0 + (size_t)64 * 64;
    const float* Bp0 = gb + (size_t)(m0 + ra) * 64 + ca;
    const float* Bp1 = Bp0 + (size_t)64 * 64;
    float acc[2][8][4] = {};
    float4 a0 = *(const float4*)Ap0, a1 = *(const float4*)Ap1;
    float4 b0 = *(const float4*)Bp0, b1 = *(const float4*)Bp1;
    for (int k0 = 0; k0 < 64; k0 += 16) {
        As[ra][ca + 0] = f2tf32(a0.x); As[ra][ca + 1] = f2tf32(a0.y);
        As[ra][ca + 2] = f2tf32(a0.z); As[ra][ca + 3] = f2tf32(a0.w);
        As[ra + 64][ca + 0] = f2tf32(a1.x); As[ra + 64][ca + 1] = f2tf32(a1.y);
        As[ra + 64][ca + 2] = f2tf32(a1.z); As[ra + 64][ca + 3] = f2tf32(a1.w);
        Bs[ra][ca + 0] = f2tf32(b0.x); Bs[ra][ca + 1] = f2tf32(b0.y);
        Bs[ra][ca + 2] = f2tf32(b0.z); Bs[ra][ca + 3] = f2tf32(b0.w);
        Bs[ra + 64][ca + 0] = f2tf32(b1.x); Bs[ra + 64][ca + 1] = f2tf32(b1.y);
        Bs[ra + 64][ca + 2] = f2tf32(b1.z); Bs[ra + 64][ca + 3] = f2tf32(b1.w);
        __syncthreads();
        if (k0 + 16 < 64) {
            a0 = *(const float4*)(Ap0 + k0 + 16);
            a1 = *(const float4*)(Ap1 + k0 + 16);
            b0 = *(const float4*)(Bp0 + k0 + 16);
            b1 = *(const float4*)(Bp1 + k0 + 16);
        }
#pragma unroll
        for (int k8 = 0; k8 < 16; k8 += 8) {
            uint32_t af[2][4], bf[8][2];
#pragma unroll
            for (int mi = 0; mi < 2; mi++) {
                int r = wm + mi * 16 + g;
                af[mi][0] = As[r][k8 + tg];
                af[mi][1] = As[r + 8][k8 + tg];
                af[mi][2] = As[r][k8 + tg + 4];
                af[mi][3] = As[r + 8][k8 + tg + 4];
            }
#pragma unroll
            for (int nj = 0; nj < 8; nj++) {
                int n = wn + nj * 8 + g;
                bf[nj][0] = Bs[n][k8 + tg];
                bf[nj][1] = Bs[n][k8 + tg + 4];
            }
#pragma unroll
            for (int mi = 0; mi < 2; mi++)
#pragma unroll
                for (int nj = 0; nj < 8; nj++)
                    mma8(acc[mi][nj], af[mi], bf[nj]);
        }
        __syncthreads();
    }
    float* Gb = G + (size_t)bh * kN * kN;
#pragma unroll
    for (int mi = 0; mi < 2; mi++) {
#pragma unroll
        for (int nj = 0; nj < 8; nj++) {
            int r0 = n0 + wm + mi * 16 + g;
            int c = m0 + wn + nj * 8 + tg * 2;
            *(float2*)&Gb[(size_t)r0 * kN + c] =
                make_float2(acc[mi][nj][0], acc[mi][nj][1]);
            *(float2*)&Gb[(size_t)(r0 + 8) * kN + c] =
                make_float2(acc[mi][nj][2], acc[mi][nj][3]);
        }
    }
}

// ------- vs[bh][k][d] = V[b,k,h,d] * inv[bh,k]  (contiguous per head) --------
__global__ __launch_bounds__(256) void vscale_kernel(const float* __restrict__ qkv,
                                                     const float* __restrict__ inv,
                                                     float* __restrict__ vs) {
    int idx = blockIdx.x * 256 + threadIdx.x;       // over kBH*kN*16 float4s
    int d4 = (idx & 15) * 4;
    int k  = (idx >> 4) & 1023;
    int bh = idx >> 14;
    int b = bh / kH, h = bh % kH;
    float iv = inv[bh * kN + k];
    float4 v = *(const float4*)(qkv + (size_t)(b * kN + k) * kQD + 2 * kD + h * kHD + d4);
    v.x *= iv; v.y *= iv; v.z *= iv; v.w *= iv;
    *(float4*)(vs + (size_t)bh * kN * kHD + (size_t)k * kHD + d4) = v;
}

// ------- out = A @ Vs (NN), tf32, 3-stage cp.async; heads merged into ctx -----
__global__ __launch_bounds__(256) void av_tf32(const float* __restrict__ Sa,
                                               const float* __restrict__ vs,
                                               float* __restrict__ ctx) {
    __shared__ __align__(16) uint32_t As[3][128][20];
    __shared__ __align__(16) uint32_t Bs[3][16][72];
    int bh = blockIdx.z, b = bh / kH, h = bh % kH;
    const float* Ab = Sa + (size_t)bh * kN * kN;
    const float* vb = vs + (size_t)bh * kN * kHD;
    int tid = threadIdx.x, lane = tid & 31, warp = tid >> 5;
    int g = lane >> 2, tg = lane & 3;
    int wm = (warp >> 1) * 32, wn = (warp & 1) * 32;
    int row0 = blockIdx.y * 128;
    int ra = tid >> 2, ca = (tid & 3) * 4;
    int kr = tid >> 4, nc = (tid & 15) * 4;
    const float* Ap0 = Ab + (size_t)(row0 + ra) * kN + ca;
    const float* Ap1 = Ap0 + (size_t)64 * kN;
    const float* Vp  = vb + (size_t)kr * kHD + nc;
    float acc[2][4][4] = {};
    auto issue = [&](int k0, int s) {
        if (k0 < kN) {
            cp16(&As[s][ra][ca],      Ap0 + k0);
            cp16(&As[s][ra + 64][ca], Ap1 + k0);
            cp16(&Bs[s][kr][nc],      Vp + (size_t)k0 * kHD);
        }
        cp_commit();
    };
    issue(0, 0);
    issue(16, 1);
    int s = 0;
    for (int k0 = 0; k0 < kN; k0 += 16) {
        cp_wait1();
        __syncthreads();
        int s2n = s + 2 >= 3 ? s - 1 : s + 2;
        issue(k0 + 32, s2n);
#pragma unroll
        for (int k8 = 0; k8 < 16; k8 += 8) {
            uint32_t af[2][4], bf[4][2];
#pragma unroll
            for (int mi = 0; mi < 2; mi++) {
                int r = wm + mi * 16 + g;
                af[mi][0] = As[s][r][k8 + tg];
                af[mi][1] = As[s][r + 8][k8 + tg];
                af[mi][2] = As[s][r][k8 + tg + 4];
                af[mi][3] = As[s][r + 8][k8 + tg + 4];
            }
#pragma unroll
            for (int nj = 0; nj < 4; nj++) {
                int n = wn + nj * 8 + g;
                bf[nj][0] = Bs[s][k8 + tg][n];
                bf[nj][1] = Bs[s][k8 + tg + 4][n];
            }
#pragma unroll
            for (int mi = 0; mi < 2; mi++)
#pragma unroll
                for (int nj = 0; nj < 4; nj++)
                    mma8(acc[mi][nj], af[mi], bf[nj]);
        }
        s = s + 1 >= 3 ? 0 : s + 1;
    }
#pragma unroll
    for (int mi = 0; mi < 2; mi++) {
#pragma unroll
        for (int nj = 0; nj < 4; nj++) {
            int tok0 = b * kN + row0 + wm + mi * 16 + g;
            int c = h * kHD + wn + nj * 8 + tg * 2;
            *(float2*)&ctx[(size_t)tok0 * kD + c] =
                make_float2(acc[mi][nj][0], acc[mi][nj][1]);
            *(float2*)&ctx[(size_t)(tok0 + 8) * kD + c] =
                make_float2(acc[mi][nj][2], acc[mi][nj][3]);
        }
    }
}

// ---- group weights: gw = softmax(gelu(V @ gp^T)) padded to 64 ----
__global__ __launch_bounds__(256) void gw_kernel(const float* __restrict__ qkv,
                                                 const float* __restrict__ gp_w,
                                                 float* __restrict__ gw) {
    __shared__ __align__(16) float gps[kGP][68];
    __shared__ __align__(16) float Vs[64][68];
    int bh = blockIdx.y;
    int b = bh / kH, h = bh % kH;
    int n0 = blockIdx.x * 64;
    int tid = threadIdx.x;
    const float* gph = gp_w + (size_t)h * kGP * kHD;
    for (int i = tid; i < kGP * 16; i += 256) {
        int r = i >> 4, c4 = (i & 15) * 4;
        *(float4*)&gps[r][c4] = *(const float4*)(gph + r * kHD + c4);
    }
    const float* vb = qkv + (size_t)(b * kN + n0) * kQD + 2 * kD + h * kHD;
    for (int i = tid; i < 64 * 16; i += 256) {
        int r = i >> 4, c4 = (i & 15) * 4;
        *(float4*)&Vs[r][c4] = *(const float4*)(vb + (size_t)r * kQD + c4);
    }
    __syncthreads();
    int r = tid >> 2;
    int c0 = tid & 3;
    float val[13];
    float mx = -1e30f;
#pragma unroll
    for (int j = 0; j < 13; j++) {
        int c = c0 + 4 * j;
        float acc = 0.f;
        if (c < kGP) {
#pragma unroll
            for (int d = 0; d < kHD; d += 4) {
                float4 vv = *(const float4*)&Vs[r][d];
                float4 gg = *(const float4*)&gps[c][d];
                acc += vv.x * gg.x + vv.y * gg.y + vv.z * gg.z + vv.w * gg.w;
            }
            acc = gelu_exact(acc);
            mx = fmaxf(mx, acc);
        }
        val[j] = acc;
    }
    mx = fmaxf(mx, __shfl_xor_sync(0xffffffffu, mx, 1));
    mx = fmaxf(mx, __shfl_xor_sync(0xffffffffu, mx, 2));
    float sum = 0.f;
#pragma unroll
    for (int j = 0; j < 13; j++) {
        int c = c0 + 4 * j;
        val[j] = (c < kGP) ? __expf(val[j] - mx) : 0.f;
        sum += val[j];
    }
    sum += __shfl_xor_sync(0xffffffffu, sum, 1);
    sum += __shfl_xor_sync(0xffffffffu, sum, 2);
    float is = 1.f / sum;
    float* grow = gw + (size_t)(bh * kN + n0 + r) * 64;
#pragma unroll
    for (int j = 0; j < 16; j++) {
        int c = c0 + 4 * j;
        if (c < 64) grow[c] = (j < 13 && c < kGP) ? val[j] * is : 0.f;
    }
}

// ------- per-row: P = softmax(S*G); A = (1-a)P + a*G  (A overwrites S) -------
__global__ __launch_bounds__(256) void rowmix_kernel(const float* __restrict__ alpha,
                                                     float* __restrict__ S,
                                                     const float* __restrict__ G) {
    __shared__ float sh1[8];
    int gr = blockIdx.x;                 // bh*N + n
    int h = (gr >> 10) % kH;
    size_t off = (size_t)gr * kN;
    int t = threadIdx.x;
    float a = 1.f / (1.f + __expf(-alpha[h]));
    float4 sv = *(const float4*)&S[off + t * 4];
    float4 gv = *(const float4*)&G[off + t * 4];
    float tv[4] = { sv.x * gv.x, sv.y * gv.y, sv.z * gv.z, sv.w * gv.w };
    float mx = fmaxf(fmaxf(tv[0], tv[1]), fmaxf(tv[2], tv[3]));
    for (int o = 16; o; o >>= 1) mx = fmaxf(mx, __shfl_xor_sync(0xffffffffu, mx, o));
    if ((t & 31) == 0) sh1[t >> 5] = mx;
    __syncthreads();
    mx = sh1[t & 7];
    for (int o = 4; o; o >>= 1) mx = fmaxf(mx, __shfl_xor_sync(0xffffffffu, mx, o));
    __syncthreads();
    float e[4], sum = 0.f;
#pragma unroll
    for (int i = 0; i < 4; i++) { e[i] = __expf(tv[i] - mx); sum += e[i]; }
    for (int o = 16; o; o >>= 1) sum += __shfl_xor_sync(0xffffffffu, sum, o);
    if ((t & 31) == 0) sh1[t >> 5] = sum;
    __syncthreads();
    sum = sh1[t & 7];
    for (int o = 4; o; o >>= 1) sum += __shfl_xor_sync(0xffffffffu, sum, o);
    float isum = (1.f - a) / sum;
    float4 o4;
    o4.x = e[0] * isum + a * gv.x;
    o4.y = e[1] * isum + a * gv.y;
    o4.z = e[2] * isum + a * gv.z;
    o4.w = e[3] * isum + a * gv.w;
    *(float4*)&S[off + t * 4] = o4;
}

// ------- column sums over n (axis=2), stores 1/(sum+1e-8) -------
__global__ __launch_bounds__(256) void colsum_kernel(const float* __restrict__ Sa,
                                                     float* __restrict__ inv) {
    int idx = blockIdx.x * 256 + threadIdx.x;   // bh*N + m
    int bh = idx >> 10, m = idx & 1023;
    const float* p = Sa + (size_t)bh * kN * kN + m;
    float s0 = 0.f, s1 = 0.f, s2 = 0.f, s3 = 0.f;
    float s4 = 0.f, s5 = 0.f, s6 = 0.f, s7 = 0.f;
#pragma unroll 4
    for (int n = 0; n < kN; n += 8) {
        s0 += p[(size_t)(n + 0) * kN];
        s1 += p[(size_t)(n + 1) * kN];
        s2 += p[(size_t)(n + 2) * kN];
        s3 += p[(size_t)(n + 3) * kN];
        s4 += p[(size_t)(n + 4) * kN];
        s5 += p[(size_t)(n + 5) * kN];
        s6 += p[(size_t)(n + 6) * kN];
        s7 += p[(size_t)(n + 7) * kN];
    }
    float s = ((s0 + s1) + (s2 + s3)) + ((s4 + s5) + (s6 + s7));
    inv[idx] = 1.f / (s + 1e-8f);
}

// ---------------- launch ----------------
extern "C" void kernel_launch(void* const* d_in, const int* in_sizes, int n_in,
                              void* d_out, int out_size) {
    const float* x      = (const float*)d_in[0];
    const float* ln1_w  = (const float*)d_in[1];
    const float* ln1_b  = (const float*)d_in[2];
    const float* qkv_w  = (const float*)d_in[3];
    const float* qkv_b  = (const float*)d_in[4];
    const float* proj_w = (const float*)d_in[5];
    const float* proj_b = (const float*)d_in[6];
    const float* gp_w   = (const float*)d_in[7];
    const float* alpha  = (const float*)d_in[8];
    const float* ln2_w  = (const float*)d_in[9];
    const float* ln2_b  = (const float*)d_in[10];
    const float* ff1_w  = (const float*)d_in[11];
    const float* ff1_b  = (const float*)d_in[12];
    const float* ff2_w  = (const float*)d_in[13];
    const float* ff2_b  = (const float*)d_in[14];
    float* out = (float*)d_out;

    float *xn, *qkv, *S, *G, *gw, *inv, *vs, *ctx, *y, *yn, *hdn;
    cudaGetSymbolAddress((void**)&xn,  g_xn);
    cudaGetSymbolAddress((void**)&qkv, g_qkv);
    cudaGetSymbolAddress((void**)&S,   g_S);
    cudaGetSymbolAddress((void**)&G,   g_G);
    cudaGetSymbolAddress((void**)&gw,  g_gw);
    cudaGetSymbolAddress((void**)&inv, g_inv);
    cudaGetSymbolAddress((void**)&vs,  g_vs);
    cudaGetSymbolAddress((void**)&ctx, g_ctx);
    cudaGetSymbolAddress((void**)&y,   g_y);
    cudaGetSymbolAddress((void**)&yn,  g_yn);
    cudaGetSymbolAddress((void**)&hdn, g_hdn);

    cudaFuncSetAttribute(gemm_nn_tf32,
                         cudaFuncAttributeMaxDynamicSharedMemorySize, kGemmSmem);

    // attention branch
    ln_kernel<<<kT, 256>>>(x, ln1_w, ln1_b, xn);
    gemm_nn_tf32<<<dim3(kQD / 128, kT / 128), 256, kGemmSmem>>>(
        xn, qkv_w, qkv_b, nullptr, qkv, kT, kQD, kD, 0);
    score_tf32<<<dim3(8, 8, kBH), 256>>>(qkv, S);
    gw_kernel<<<dim3(kN / 64, kBH), 256>>>(qkv, gp_w, gw);
    gmat_tf32<<<dim3(8, 8, kBH), 256>>>(gw, G);
    rowmix_kernel<<<kBH * kN, 256>>>(alpha, S, G);
    colsum_kernel<<<kBH * kN / 256, 256>>>(S, inv);
    vscale_kernel<<<kBH * kN * 16 / 256, 256>>>(qkv, inv, vs);
    av_tf32<<<dim3(1, 8, kBH), 256>>>(S, vs, ctx);
    gemm_nn_tf32<<<dim3(kD / 128, kT / 128), 256, kGemmSmem>>>(
        ctx, proj_w, proj_b, x, y, kT, kD, kD, 0);
    // FFN branch
    ln_kernel<<<kT, 256>>>(y, ln2_w, ln2_b, yn);
    gemm_nn_tf32<<<dim3(kMLP / 128, kT / 128), 256, kGemmSmem>>>(
        yn, ff1_w, ff1_b, nullptr, hdn, kT, kMLP, kD, 1);
    gemm_nn_tf32<<<dim3(kD / 128, kT / 128), 256, kGemmSmem>>>(
        hdn, ff2_w, ff2_b, y, out, kT, kD, kMLP, 0);
}

// round 12
// speedup vs baseline: 1.2378x; 1.0421x over previous
#include <cuda_runtime.h>
#include <cuda_fp16.h>
#include <math.h>
#include <stdint.h>

// ---------------- problem constants ----------------
namespace {
constexpr int kB  = 4;
constexpr int kN  = 1024;
constexpr int kD  = 768;
constexpr int kH  = 12;
constexpr int kHD = 64;
constexpr int kGP = 49;
constexpr int kMLP = 3072;
constexpr int kT  = kB * kN;     // 4096 tokens
constexpr int kBH = kB * kH;     // 48 batched heads
constexpr int kQD = 3 * kD;      // 2304
constexpr int kGemmSmem = 4 * (128 * 20 + 16 * 136) * 4;
}

// ---------------- scratch (device globals: no allocation allowed) ----------------
__device__ float  g_xn [kT * kD];
__device__ float  g_qkv[kT * kQD];
__device__ __half g_S  [(size_t)kBH * kN * kN];  // fp16 scores, later mixed attn A
__device__ float  g_G  [(size_t)kBH * kN * kN];  // gw @ gw^T (fp32: feeds output linearly)
__device__ float  g_gw [kBH * kN * 64];          // softmaxed group weights, padded 49->64
__device__ float  g_inv[kBH * kN];               // 1/(colsum+eps)
__device__ __half g_vs [(size_t)kBH * kHD * kN]; // inv-scaled V, TRANSPOSED [bh][d][k], fp16
__device__ float  g_ctx[kT * kD];                // merged-head attention output
__device__ float  g_y  [kT * kD];                // after proj residual
__device__ float  g_yn [kT * kD];
__device__ float  g_hdn[kT * kMLP];

__device__ __forceinline__ float gelu_exact(float x) {
    return 0.5f * x * (1.0f + erff(x * 0.70710678118654752440f));
}

__device__ __forceinline__ uint32_t f2tf32(float x) {
    uint32_t r;
    asm("cvt.rna.tf32.f32 %0, %1;" : "=r"(r) : "f"(x));
    return r;
}

__device__ __forceinline__ void cp16(void* dst_smem, const void* src_gmem) {
    uint32_t d = (uint32_t)__cvta_generic_to_shared(dst_smem);
    asm volatile("cp.async.cg.shared.global [%0], [%1], 16;" :: "r"(d), "l"(src_gmem));
}
__device__ __forceinline__ void cp_commit() {
    asm volatile("cp.async.commit_group;");
}
__device__ __forceinline__ void cp_wait1() {
    asm volatile("cp.async.wait_group 1;");
}
__device__ __forceinline__ void cp_wait2() {
    asm volatile("cp.async.wait_group 2;");
}

// D += A(m16k8,row) * B(k8n8,col)   tf32
__device__ __forceinline__ void mma8(float* c, const uint32_t* a, const uint32_t* b) {
    asm volatile("mma.sync.aligned.m16n8k8.row.col.f32.tf32.tf32.f32 "
                 "{%0,%1,%2,%3}, {%4,%5,%6,%7}, {%8,%9}, {%0,%1,%2,%3};"
                 : "+f"(c[0]), "+f"(c[1]), "+f"(c[2]), "+f"(c[3])
                 : "r"(a[0]), "r"(a[1]), "r"(a[2]), "r"(a[3]),
                   "r"(b[0]), "r"(b[1]));
}

// D += A(m16k16,row,f16) * B(k16n8,col,f16), fp32 accum
__device__ __forceinline__ void mma16h(float* c, const uint32_t* a, const uint32_t* b) {
    asm volatile("mma.sync.aligned.m16n8k16.row.col.f32.f16.f16.f32 "
                 "{%0,%1,%2,%3}, {%4,%5,%6,%7}, {%8,%9}, {%0,%1,%2,%3};"
                 : "+f"(c[0]), "+f"(c[1]), "+f"(c[2]), "+f"(c[3])
                 : "r"(a[0]), "r"(a[1]), "r"(a[2]), "r"(a[3]),
                   "r"(b[0]), "r"(b[1]));
}

// ---------------- LayerNorm: one block (256 thr) per row of 768 ----------------
__global__ __launch_bounds__(256) void ln_kernel(const float* __restrict__ x,
                                                 const float* __restrict__ w,
                                                 const float* __restrict__ b,
                                                 float* __restrict__ out) {
    __shared__ float sh1[8], sh2[8];
    int row = blockIdx.x;
    int t = threadIdx.x;
    const float* xr = x + (size_t)row * kD;
    float v[3];
    float s = 0.f, s2 = 0.f;
#pragma unroll
    for (int i = 0; i < 3; i++) {
        v[i] = xr[t + i * 256];
        s  += v[i];
        s2 += v[i] * v[i];
    }
#pragma unroll
    for (int o = 16; o; o >>= 1) {
        s  += __shfl_xor_sync(0xffffffffu, s, o);
        s2 += __shfl_xor_sync(0xffffffffu, s2, o);
    }
    if ((t & 31) == 0) { sh1[t >> 5] = s; sh2[t >> 5] = s2; }
    __syncthreads();
    s = sh1[t & 7]; s2 = sh2[t & 7];
#pragma unroll
    for (int o = 4; o; o >>= 1) {
        s  += __shfl_xor_sync(0xffffffffu, s, o);
        s2 += __shfl_xor_sync(0xffffffffu, s2, o);
    }
    float mu   = s * (1.0f / kD);
    float var  = fmaxf(s2 * (1.0f / kD) - mu * mu, 0.f);
    float rstd = rsqrtf(var + 1e-5f);
    float* orow = out + (size_t)row * kD;
#pragma unroll
    for (int i = 0; i < 3; i++) {
        int c = t + i * 256;
        orow[c] = (v[i] - mu) * rstd * w[c] + b[c];
    }
}

// ------- TF32 dense GEMM (NN): C = A@B + bias (+gelu)(+res) -------------------
// 128x128 block, 8 warps, K-step 16, 4-stage cp.async pipeline (raw fp32 bits).
__global__ __launch_bounds__(256) void gemm_nn_tf32(
        const float* __restrict__ A, const float* __restrict__ B,
        const float* __restrict__ bias, const float* __restrict__ res,
        float* __restrict__ C, int M, int N, int K, int act) {
    extern __shared__ uint32_t dsm[];
    uint32_t* AsBuf = dsm;                      // [4][128*20]
    uint32_t* BsBuf = dsm + 4 * 128 * 20;       // [4][16*136]
#define GAS(s, r, c) AsBuf[(s) * 2560 + (r) * 20 + (c)]
#define GBS(s, r, c) BsBuf[(s) * 2176 + (r) * 136 + (c)]
    int tid = threadIdx.x, lane = tid & 31, warp = tid >> 5;
    int g = lane >> 2, tg = lane & 3;
    int wm = (warp >> 1) * 32, wn = (warp & 1) * 64;
    int row0 = blockIdx.y * 128, col0 = blockIdx.x * 128;
    int ra = tid >> 2, ca = (tid & 3) * 4;       // A loader coords
    int kb = tid >> 5, nb = (tid & 31) * 4;      // B loader coords
    const float* Abase  = A + (size_t)(row0 + ra) * K + ca;
    const float* Abase2 = A + (size_t)(row0 + ra + 64) * K + ca;
    const float* Bbase  = B + (size_t)kb * N + col0 + nb;
    const float* Bbase2 = B + (size_t)(kb + 8) * N + col0 + nb;
    float acc[2][8][4] = {};

    auto issue = [&](int k0, int s) {
        if (k0 < K) {
            cp16(&GAS(s, ra, ca),      Abase + k0);
            cp16(&GAS(s, ra + 64, ca), Abase2 + k0);
            cp16(&GBS(s, kb, nb),      Bbase + (size_t)k0 * N);
            cp16(&GBS(s, kb + 8, nb),  Bbase2 + (size_t)k0 * N);
        }
        cp_commit();
    };
    issue(0, 0);
    issue(16, 1);
    issue(32, 2);
    int s = 0;
    for (int k0 = 0; k0 < K; k0 += 16) {
        cp_wait2();
        __syncthreads();
        issue(k0 + 48, (s + 3) & 3);
#pragma unroll
        for (int k8 = 0; k8 < 16; k8 += 8) {
            uint32_t af[2][4], bf[8][2];
#pragma unroll
            for (int mi = 0; mi < 2; mi++) {
                int r = wm + mi * 16 + g;
                af[mi][0] = GAS(s, r, k8 + tg);
                af[mi][1] = GAS(s, r + 8, k8 + tg);
                af[mi][2] = GAS(s, r, k8 + tg + 4);
                af[mi][3] = GAS(s, r + 8, k8 + tg + 4);
            }
#pragma unroll
            for (int nj = 0; nj < 8; nj++) {
                int n = wn + nj * 8 + g;
                bf[nj][0] = GBS(s, k8 + tg, n);
                bf[nj][1] = GBS(s, k8 + tg + 4, n);
            }
#pragma unroll
            for (int mi = 0; mi < 2; mi++)
#pragma unroll
                for (int nj = 0; nj < 8; nj++)
                    mma8(acc[mi][nj], af[mi], bf[nj]);
        }
        s = (s + 1) & 3;
    }
#undef GAS
#undef GBS
#pragma unroll
    for (int mi = 0; mi < 2; mi++) {
#pragma unroll
        for (int nj = 0; nj < 8; nj++) {
            int r0 = row0 + wm + mi * 16 + g;
            int c = col0 + wn + nj * 8 + tg * 2;
            float b0 = bias[c], b1 = bias[c + 1];
            float o00 = acc[mi][nj][0] + b0, o01 = acc[mi][nj][1] + b1;
            float o10 = acc[mi][nj][2] + b0, o11 = acc[mi][nj][3] + b1;
            if (act) {
                o00 = gelu_exact(o00); o01 = gelu_exact(o01);
                o10 = gelu_exact(o10); o11 = gelu_exact(o11);
            }
            if (res) {
                o00 += res[(size_t)r0 * N + c];       o01 += res[(size_t)r0 * N + c + 1];
                o10 += res[(size_t)(r0 + 8) * N + c]; o11 += res[(size_t)(r0 + 8) * N + c + 1];
            }
            *(float2*)&C[(size_t)r0 * N + c]       = make_float2(o00, o01);
            *(float2*)&C[(size_t)(r0 + 8) * N + c] = make_float2(o10, o11);
        }
    }
}

// ------- scores S = scale * Q @ K^T (NT), tf32 compute, fp16 store ------------
__global__ __launch_bounds__(256) void score_tf32(const float* __restrict__ qkv,
                                                  __half* __restrict__ S) {
    __shared__ uint32_t As[128][20];
    __shared__ uint32_t Bs[128][20];
    int bh = blockIdx.z, b = bh / kH, h = bh % kH;
    const float* qb = qkv + (size_t)b * kN * kQD + h * kHD;
    const float* kb = qb + kD;
    int tid = threadIdx.x, lane = tid & 31, warp = tid >> 5;
    int g = lane >> 2, tg = lane & 3;
    int wm = (warp >> 1) * 32, wn = (warp & 1) * 64;
    int n0 = blockIdx.y * 128, m0 = blockIdx.x * 128;
    int ra = tid >> 2, ca = (tid & 3) * 4;
    const float* Qp0 = qb + (size_t)(n0 + ra) * kQD + ca;
    const float* Qp1 = Qp0 + (size_t)64 * kQD;
    const float* Kp0 = kb + (size_t)(m0 + ra) * kQD + ca;
    const float* Kp1 = Kp0 + (size_t)64 * kQD;
    float acc[2][8][4] = {};
    float4 q0 = *(const float4*)Qp0, q1 = *(const float4*)Qp1;
    float4 v0 = *(const float4*)Kp0, v1 = *(const float4*)Kp1;
    for (int k0 = 0; k0 < kHD; k0 += 16) {
        As[ra][ca + 0] = f2tf32(q0.x); As[ra][ca + 1] = f2tf32(q0.y);
        As[ra][ca + 2] = f2tf32(q0.z); As[ra][ca + 3] = f2tf32(q0.w);
        As[ra + 64][ca + 0] = f2tf32(q1.x); As[ra + 64][ca + 1] = f2tf32(q1.y);
        As[ra + 64][ca + 2] = f2tf32(q1.z); As[ra + 64][ca + 3] = f2tf32(q1.w);
        Bs[ra][ca + 0] = f2tf32(v0.x); Bs[ra][ca + 1] = f2tf32(v0.y);
        Bs[ra][ca + 2] = f2tf32(v0.z); Bs[ra][ca + 3] = f2tf32(v0.w);
        Bs[ra + 64][ca + 0] = f2tf32(v1.x); Bs[ra + 64][ca + 1] = f2tf32(v1.y);
        Bs[ra + 64][ca + 2] = f2tf32(v1.z); Bs[ra + 64][ca + 3] = f2tf32(v1.w);
        __syncthreads();
        if (k0 + 16 < kHD) {
            q0 = *(const float4*)(Qp0 + k0 + 16);
            q1 = *(const float4*)(Qp1 + k0 + 16);
            v0 = *(const float4*)(Kp0 + k0 + 16);
            v1 = *(const float4*)(Kp1 + k0 + 16);
        }
#pragma unroll
        for (int k8 = 0; k8 < 16; k8 += 8) {
            uint32_t af[2][4], bf[8][2];
#pragma unroll
            for (int mi = 0; mi < 2; mi++) {
                int r = wm + mi * 16 + g;
                af[mi][0] = As[r][k8 + tg];
                af[mi][1] = As[r + 8][k8 + tg];
                af[mi][2] = As[r][k8 + tg + 4];
                af[mi][3] = As[r + 8][k8 + tg + 4];
            }
#pragma unroll
            for (int nj = 0; nj < 8; nj++) {
                int n = wn + nj * 8 + g;
                bf[nj][0] = Bs[n][k8 + tg];
                bf[nj][1] = Bs[n][k8 + tg + 4];
            }
#pragma unroll
            for (int mi = 0; mi < 2; mi++)
#pragma unroll
                for (int nj = 0; nj < 8; nj++)
                    mma8(acc[mi][nj], af[mi], bf[nj]);
        }
        __syncthreads();
    }
    __half* Sb = S + (size_t)bh * kN * kN;
#pragma unroll
    for (int mi = 0; mi < 2; mi++) {
#pragma unroll
        for (int nj = 0; nj < 8; nj++) {
            int r0 = n0 + wm + mi * 16 + g;
            int c = m0 + wn + nj * 8 + tg * 2;
            *(__half2*)&Sb[(size_t)r0 * kN + c] =
                __floats2half2_rn(acc[mi][nj][0] * 0.125f, acc[mi][nj][1] * 0.125f);
            *(__half2*)&Sb[(size_t)(r0 + 8) * kN + c] =
                __floats2half2_rn(acc[mi][nj][2] * 0.125f, acc[mi][nj][3] * 0.125f);
        }
    }
}

// ---------------- G = gw @ gw^T (NT), tf32, K=64 padded ----------------
__global__ __launch_bounds__(256) void gmat_tf32(const float* __restrict__ gw,
                                                 float* __restrict__ G) {
    __shared__ uint32_t As[128][20];
    __shared__ uint32_t Bs[128][20];
    int bh = blockIdx.z;
    const float* gb = gw + (size_t)bh * kN * 64;
    int tid = threadIdx.x, lane = tid & 31, warp = tid >> 5;
    int g = lane >> 2, tg = lane & 3;
    int wm = (warp >> 1) * 32, wn = (warp & 1) * 64;
    int n0 = blockIdx.y * 128, m0 = blockIdx.x * 128;
    int ra = tid >> 2, ca = (tid & 3) * 4;
    const float* Ap0 = gb + (size_t)(n0 + ra) * 64 + ca;
    const float* Ap1 = Ap0 + (size_t)64 * 64;
    const float* Bp0 = gb + (size_t)(m0 + ra) * 64 + ca;
    const float* Bp1 = Bp0 + (size_t)64 * 64;
    float acc[2][8][4] = {};
    float4 a0 = *(const float4*)Ap0, a1 = *(const float4*)Ap1;
    float4 b0 = *(const float4*)Bp0, b1 = *(const float4*)Bp1;
    for (int k0 = 0; k0 < 64; k0 += 16) {
        As[ra][ca + 0] = f2tf32(a0.x); As[ra][ca + 1] = f2tf32(a0.y);
        As[ra][ca + 2] = f2tf32(a0.z); As[ra][ca + 3] = f2tf32(a0.w);
        As[ra + 64][ca + 0] = f2tf32(a1.x); As[ra + 64][ca + 1] = f2tf32(a1.y);
        As[ra + 64][ca + 2] = f2tf32(a1.z); As[ra + 64][ca + 3] = f2tf32(a1.w);
        Bs[ra][ca + 0] = f2tf32(b0.x); Bs[ra][ca + 1] = f2tf32(b0.y);
        Bs[ra][ca + 2] = f2tf32(b0.z); Bs[ra][ca + 3] = f2tf32(b0.w);
        Bs[ra + 64][ca + 0] = f2tf32(b1.x); Bs[ra + 64][ca + 1] = f2tf32(b1.y);
        Bs[ra + 64][ca + 2] = f2tf32(b1.z); Bs[ra + 64][ca + 3] = f2tf32(b1.w);
        __syncthreads();
        if (k0 + 16 < 64) {
            a0 = *(const float4*)(Ap0 + k0 + 16);
            a1 = *(const float4*)(Ap1 + k0 + 16);
            b0 = *(const float4*)(Bp0 + k0 + 16);
            b1 = *(const float4*)(Bp1 + k0 + 16);
        }
#pragma unroll
        for (int k8 = 0; k8 < 16; k8 += 8) {
            uint32_t af[2][4], bf[8][2];
#pragma unroll
            for (int mi = 0; mi < 2; mi++) {
                int r = wm + mi * 16 + g;
                af[mi][0] = As[r][k8 + tg];
                af[mi][1] = As[r + 8][k8 + tg];
                af[mi][2] = As[r][k8 + tg + 4];
                af[mi][3] = As[r + 8][k8 + tg + 4];
            }
#pragma unroll
            for (int nj = 0; nj < 8; nj++) {
                int n = wn + nj * 8 + g;
                bf[nj][0] = Bs[n][k8 + tg];
                bf[nj][1] = Bs[n][k8 + tg + 4];
            }
#pragma unroll
            for (int mi = 0; mi < 2; mi++)
#pragma unroll
                for (int nj = 0; nj < 8; nj++)
                    mma8(acc[mi][nj], af[mi], bf[nj]);
        }
        __syncthreads();
    }
    float* Gb = G + (size_t)bh * kN * kN;
#pragma unroll
    for (int mi = 0; mi < 2; mi++) {
#pragma unroll
        for (int nj = 0; nj < 8; nj++) {
            int r0 = n0 + wm + mi * 16 + g;
            int c = m0 + wn + nj * 8 + tg * 2;
            *(float2*)&Gb[(size_t)r0 * kN + c] =
                make_float2(acc[mi][nj][0], acc[mi][nj][1]);
            *(float2*)&Gb[(size_t)(r0 + 8) * kN + c] =
                make_float2(acc[mi][nj][2], acc[mi][nj][3]);
        }
    }
}

// ------- per-row: P = softmax(S*G); A = (1-a)P + a*G  (fp16 S in/out) --------
__global__ __launch_bounds__(256) void rowmix_kernel(const float* __restrict__ alpha,
                                                     __half* __restrict__ S,
                                                     const float* __restrict__ G) {
    __shared__ float sh1[8];
    int gr = blockIdx.x;                 // bh*N + n
    int h = (gr >> 10) % kH;
    size_t off = (size_t)gr * kN;
    int t = threadIdx.x;
    float a = 1.f / (1.f + __expf(-alpha[h]));
    __half2* Sh = (__half2*)(S + off);
    __half2 p0 = Sh[t * 2], p1 = Sh[t * 2 + 1];
    float2 f0 = __half22float2(p0), f1 = __half22float2(p1);
    float4 gv = *(const float4*)&G[off + t * 4];
    float tv[4] = { f0.x * gv.x, f0.y * gv.y, f1.x * gv.z, f1.y * gv.w };
    float mx = fmaxf(fmaxf(tv[0], tv[1]), fmaxf(tv[2], tv[3]));
    for (int o = 16; o; o >>= 1) mx = fmaxf(mx, __shfl_xor_sync(0xffffffffu, mx, o));
    if ((t & 31) == 0) sh1[t >> 5] = mx;
    __syncthreads();
    mx = sh1[t & 7];
    for (int o = 4; o; o >>= 1) mx = fmaxf(mx, __shfl_xor_sync(0xffffffffu, mx, o));
    __syncthreads();
    float e[4], sum = 0.f;
#pragma unroll
    for (int i = 0; i < 4; i++) { e[i] = __expf(tv[i] - mx); sum += e[i]; }
    for (int o = 16; o; o >>= 1) sum += __shfl_xor_sync(0xffffffffu, sum, o);
    if ((t & 31) == 0) sh1[t >> 5] = sum;
    __syncthreads();
    sum = sh1[t & 7];
    for (int o = 4; o; o >>= 1) sum += __shfl_xor_sync(0xffffffffu, sum, o);
    float isum = (1.f - a) / sum;
    Sh[t * 2]     = __floats2half2_rn(e[0] * isum + a * gv.x, e[1] * isum + a * gv.y);
    Sh[t * 2 + 1] = __floats2half2_rn(e[2] * isum + a * gv.z, e[3] * isum + a * gv.w);
}

// ------- column sums over n (axis=2), fp16 A, stores 1/(sum+1e-8) -------
__global__ __launch_bounds__(256) void colsum_kernel(const __half* __restrict__ Sa,
                                                     float* __restrict__ inv) {
    int idx = blockIdx.x * 256 + threadIdx.x;   // bh*N + m
    int bh = idx >> 10, m = idx & 1023;
    const __half* p = Sa + (size_t)bh * kN * kN + m;
    float s0 = 0.f, s1 = 0.f, s2 = 0.f, s3 = 0.f;
    float s4 = 0.f, s5 = 0.f, s6 = 0.f, s7 = 0.f;
#pragma unroll 4
    for (int n = 0; n < kN; n += 8) {
        s0 += __half2float(p[(size_t)(n + 0) * kN]);
        s1 += __half2float(p[(size_t)(n + 1) * kN]);
        s2 += __half2float(p[(size_t)(n + 2) * kN]);
        s3 += __half2float(p[(size_t)(n + 3) * kN]);
        s4 += __half2float(p[(size_t)(n + 4) * kN]);
        s5 += __half2float(p[(size_t)(n + 5) * kN]);
        s6 += __half2float(p[(size_t)(n + 6) * kN]);
        s7 += __half2float(p[(size_t)(n + 7) * kN]);
    }
    float s = ((s0 + s1) + (s2 + s3)) + ((s4 + s5) + (s6 + s7));
    inv[idx] = 1.f / (s + 1e-8f);
}

// ------- vs[bh][d][k] = V[b,k,h,d] * inv[bh,k]   (transposed, fp16) ----------
__global__ __launch_bounds__(256) void vscale_t_kernel(const float* __restrict__ qkv,
                                                       const float* __restrict__ inv,
                                                       __half* __restrict__ vs) {
    __shared__ __half tile[64][72];   // [d][k], padded
    int bh = blockIdx.y, k0 = blockIdx.x * 64;
    int b = bh / kH, h = bh % kH;
    int t = threadIdx.x;
    for (int i = t; i < 64 * 16; i += 256) {      // 64 k-rows x 16 float4
        int kk = i >> 4, d4 = (i & 15) * 4;
        float iv = inv[bh * kN + k0 + kk];
        float4 v = *(const float4*)(qkv + (size_t)(b * kN + k0 + kk) * kQD
                                    + 2 * kD + h * kHD + d4);
        tile[d4 + 0][kk] = __float2half_rn(v.x * iv);
        tile[d4 + 1][kk] = __float2half_rn(v.y * iv);
        tile[d4 + 2][kk] = __float2half_rn(v.z * iv);
        tile[d4 + 3][kk] = __float2half_rn(v.w * iv);
    }
    __syncthreads();
    for (int i = t; i < 64 * 8; i += 256) {       // 512 x 16B chunks
        int d = i >> 3, ch = (i & 7) * 8;
        *(uint4*)(vs + ((size_t)bh * kHD + d) * kN + k0 + ch) = *(uint4*)&tile[d][ch];
    }
}

// ------- out = A @ Vs (fp16 m16n8k16, fp32 accum), 3-stage cp.async ----------
__global__ __launch_bounds__(256) void av_f16(const __half* __restrict__ Sa,
                                              const __half* __restrict__ vs,
                                              float* __restrict__ ctx) {
    __shared__ __align__(16) __half As[3][128][24];   // stride 24 halves = 48B
    __shared__ __align__(16) __half Bs[3][64][24];    // [d][k]
    int bh = blockIdx.z, b = bh / kH, h = bh % kH;
    const __half* Ab = Sa + (size_t)bh * kN * kN;
    const __half* vb = vs + (size_t)bh * kHD * kN;    // [d][k]
    int tid = threadIdx.x, lane = tid & 31, warp = tid >> 5;
    int g = lane >> 2, tg = lane & 3;
    int wm = (warp >> 1) * 32, wn = (warp & 1) * 32;
    int row0 = blockIdx.y * 128;
    int ra = tid >> 1, cha = (tid & 1) * 8;           // A loader: 128 rows x 2 chunks
    int db = (tid & 127) >> 1, chb = (tid & 1) * 8;   // B loader: 64 rows x 2 chunks
    const __half* Ap = Ab + (size_t)(row0 + ra) * kN + cha;
    const __half* Vp = vb + (size_t)db * kN + chb;
    float acc[2][4][4] = {};
    auto issue = [&](int k0, int s) {
        if (k0 < kN) {
            cp16(&As[s][ra][cha], Ap + k0);
            if (tid < 128) cp16(&Bs[s][db][chb], Vp + k0);
        }
        cp_commit();
    };
    issue(0, 0);
    issue(16, 1);
    int s = 0;
    for (int k0 = 0; k0 < kN; k0 += 16) {
        cp_wait1();
        __syncthreads();
        int s2n = s + 2 >= 3 ? s - 1 : s + 2;
        issue(k0 + 32, s2n);
        uint32_t af[2][4], bf[4][2];
#pragma unroll
        for (int mi = 0; mi < 2; mi++) {
            int r = wm + mi * 16 + g;
            af[mi][0] = *(const uint32_t*)&As[s][r][2 * tg];
            af[mi][1] = *(const uint32_t*)&As[s][r + 8][2 * tg];
            af[mi][2] = *(const uint32_t*)&As[s][r][2 * tg + 8];
            af[mi][3] = *(const uint32_t*)&As[s][r + 8][2 * tg + 8];
        }
#pragma unroll
        for (int nj = 0; nj < 4; nj++) {
            int n = wn + nj * 8 + g;
            bf[nj][0] = *(const uint32_t*)&Bs[s][n][2 * tg];
            bf[nj][1] = *(const uint32_t*)&Bs[s][n][2 * tg + 8];
        }
#pragma unroll
        for (int mi = 0; mi < 2; mi++)
#pragma unroll
            for (int nj = 0; nj < 4; nj++)
                mma16h(acc[mi][nj], af[mi], bf[nj]);
        s = s + 1 >= 3 ? 0 : s + 1;
    }
#pragma unroll
    for (int mi = 0; mi < 2; mi++) {
#pragma unroll
        for (int nj = 0; nj < 4; nj++) {
            int tok0 = b * kN + row0 + wm + mi * 16 + g;
            int c = h * kHD + wn + nj * 8 + tg * 2;
            *(float2*)&ctx[(size_t)tok0 * kD + c] =
                make_float2(acc[mi][nj][0], acc[mi][nj][1]);
            *(float2*)&ctx[(size_t)(tok0 + 8) * kD + c] =
                make_float2(acc[mi][nj][2], acc[mi][nj][3]);
        }
    }
}

// ---- group weights: gw = softmax(gelu(V @ gp^T)) padded to 64 ----
__global__ __launch_bounds__(256) void gw_kernel(const float* __restrict__ qkv,
                                                 const float* __restrict__ gp_w,
                                                 float* __restrict__ gw) {
    __shared__ __align__(16) float gps[kGP][68];
    __shared__ __align__(16) float Vs[64][68];
    int bh = blockIdx.y;
    int b = bh / kH, h = bh % kH;
    int n0 = blockIdx.x * 64;
    int tid = threadIdx.x;
    const float* gph = gp_w + (size_t)h * kGP * kHD;
    for (int i = tid; i < kGP * 16; i += 256) {
        int r = i >> 4, c4 = (i & 15) * 4;
        *(float4*)&gps[r][c4] = *(const float4*)(gph + r * kHD + c4);
    }
    const float* vb = qkv + (size_t)(b * kN + n0) * kQD + 2 * kD + h * kHD;
    for (int i = tid; i < 64 * 16; i += 256) {
        int r = i >> 4, c4 = (i & 15) * 4;
        *(float4*)&Vs[r][c4] = *(const float4*)(vb + (size_t)r * kQD + c4);
    }
    __syncthreads();
    int r = tid >> 2;
    int c0 = tid & 3;
    float val[13];
    float mx = -1e30f;
#pragma unroll
    for (int j = 0; j < 13; j++) {
        int c = c0 + 4 * j;
        float acc = 0.f;
        if (c < kGP) {
#pragma unroll
            for (int d = 0; d < kHD; d += 4) {
                float4 vv = *(const float4*)&Vs[r][d];
                float4 gg = *(const float4*)&gps[c][d];
                acc += vv.x * gg.x + vv.y * gg.y + vv.z * gg.z + vv.w * gg.w;
            }
            acc = gelu_exact(acc);
            mx = fmaxf(mx, acc);
        }
        val[j] = acc;
    }
    mx = fmaxf(mx, __shfl_xor_sync(0xffffffffu, mx, 1));
    mx = fmaxf(mx, __shfl_xor_sync(0xffffffffu, mx, 2));
    float sum = 0.f;
#pragma unroll
    for (int j = 0; j < 13; j++) {
        int c = c0 + 4 * j;
        val[j] = (c < kGP) ? __expf(val[j] - mx) : 0.f;
        sum += val[j];
    }
    sum += __shfl_xor_sync(0xffffffffu, sum, 1);
    sum += __shfl_xor_sync(0xffffffffu, sum, 2);
    float is = 1.f / sum;
    float* grow = gw + (size_t)(bh * kN + n0 + r) * 64;
#pragma unroll
    for (int j = 0; j < 16; j++) {
        int c = c0 + 4 * j;
        if (c < 64) grow[c] = (j < 13 && c < kGP) ? val[j] * is : 0.f;
    }
}

// ---------------- launch ----------------
extern "C" void kernel_launch(void* const* d_in, const int* in_sizes, int n_in,
                              void* d_out, int out_size) {
    const float* x      = (const float*)d_in[0];
    const float* ln1_w  = (const float*)d_in[1];
    const float* ln1_b  = (const float*)d_in[2];
    const float* qkv_w  = (const float*)d_in[3];
    const float* qkv_b  = (const float*)d_in[4];
    const float* proj_w = (const float*)d_in[5];
    const float* proj_b = (const float*)d_in[6];
    const float* gp_w   = (const float*)d_in[7];
    const float* alpha  = (const float*)d_in[8];
    const float* ln2_w  = (const float*)d_in[9];
    const float* ln2_b  = (const float*)d_in[10];
    const float* ff1_w  = (const float*)d_in[11];
    const float* ff1_b  = (const float*)d_in[12];
    const float* ff2_w  = (const float*)d_in[13];
    const float* ff2_b  = (const float*)d_in[14];
    float* out = (float*)d_out;

    float *xn, *qkv, *G, *gw, *inv, *ctx, *y, *yn, *hdn;
    __half *S, *vs;
    cudaGetSymbolAddress((void**)&xn,  g_xn);
    cudaGetSymbolAddress((void**)&qkv, g_qkv);
    cudaGetSymbolAddress((void**)&S,   g_S);
    cudaGetSymbolAddress((void**)&G,   g_G);
    cudaGetSymbolAddress((void**)&gw,  g_gw);
    cudaGetSymbolAddress((void**)&inv, g_inv);
    cudaGetSymbolAddress((void**)&vs,  g_vs);
    cudaGetSymbolAddress((void**)&ctx, g_ctx);
    cudaGetSymbolAddress((void**)&y,   g_y);
    cudaGetSymbolAddress((void**)&yn,  g_yn);
    cudaGetSymbolAddress((void**)&hdn, g_hdn);

    cudaFuncSetAttribute(gemm_nn_tf32,
                         cudaFuncAttributeMaxDynamicSharedMemorySize, kGemmSmem);

    // attention branch
    ln_kernel<<<kT, 256>>>(x, ln1_w, ln1_b, xn);
    gemm_nn_tf32<<<dim3(kQD / 128, kT / 128), 256, kGemmSmem>>>(
        xn, qkv_w, qkv_b, nullptr, qkv, kT, kQD, kD, 0);
    score_tf32<<<dim3(8, 8, kBH), 256>>>(qkv, S);
    gw_kernel<<<dim3(kN / 64, kBH), 256>>>(qkv, gp_w, gw);
    gmat_tf32<<<dim3(8, 8, kBH), 256>>>(gw, G);
    rowmix_kernel<<<kBH * kN, 256>>>(alpha, S, G);
    colsum_kernel<<<kBH * kN / 256, 256>>>(S, inv);
    vscale_t_kernel<<<dim3(kN / 64, kBH), 256>>>(qkv, inv, vs);
    av_f16<<<dim3(1, 8, kBH), 256>>>(S, vs, ctx);
    gemm_nn_tf32<<<dim3(kD / 128, kT / 128), 256, kGemmSmem>>>(
        ctx, proj_w, proj_b, x, y, kT, kD, kD, 0);
    // FFN branch
    ln_kernel<<<kT, 256>>>(y, ln2_w, ln2_b, yn);
    gemm_nn_tf32<<<dim3(kMLP / 128, kT / 128), 256, kGemmSmem>>>(
        yn, ff1_w, ff1_b, nullptr, hdn, kT, kMLP, kD, 1);
    gemm_nn_tf32<<<dim3(kD / 128, kT / 128), 256, kGemmSmem>>>(
        hdn, ff2_w, ff2_b, y, out, kT, kD, kMLP, 0);
}

// round 13
// speedup vs baseline: 1.4998x; 1.2117x over previous
#include <cuda_runtime.h>
#include <cuda_fp16.h>
#include <math.h>
#include <stdint.h>

// ---------------- problem constants ----------------
namespace {
constexpr int kB  = 4;
constexpr int kN  = 1024;
constexpr int kD  = 768;
constexpr int kH  = 12;
constexpr int kHD = 64;
constexpr int kGP = 49;
constexpr int kMLP = 3072;
constexpr int kT  = kB * kN;     // 4096 tokens
constexpr int kBH = kB * kH;     // 48 batched heads
constexpr int kQD = 3 * kD;      // 2304
// fp16 gemm dynamic smem: 3 stages x (A 128x40 + B 128x40) halves
constexpr int kGemmSmemH = 3 * (128 * 40 + 128 * 40) * 2;
}

// ---------------- scratch (device globals: no allocation allowed) ----------------
__device__ __half g_xn [kT * kD];                // fp16 LN1 output
__device__ float  g_qkv[kT * kQD];
__device__ __half g_S  [(size_t)kBH * kN * kN];  // fp16 scores, later mixed attn A
__device__ float  g_G  [(size_t)kBH * kN * kN];  // gw @ gw^T
__device__ float  g_gw [kBH * kN * 64];          // softmaxed group weights, padded 49->64
__device__ float  g_inv[kBH * kN];               // 1/(colsum+eps)
__device__ __half g_vs [(size_t)kBH * kHD * kN]; // inv-scaled V, TRANSPOSED [bh][d][k]
__device__ __half g_ctx[kT * kD];                // merged-head attention output (fp16)
__device__ float  g_y  [kT * kD];                // after proj residual (fp32)
__device__ __half g_yn [kT * kD];                // fp16 LN2 output
__device__ __half g_hdn[kT * kMLP];              // fp16 gelu(ff1)
// transposed fp16 weights
__device__ __half g_qkvwt[kQD * kD];             // [N=2304][K=768]
__device__ __half g_projwt[kD * kD];
__device__ __half g_ff1wt [kMLP * kD];           // [3072][768]
__device__ __half g_ff2wt [kD * kMLP];           // [768][3072]

__device__ __forceinline__ float gelu_exact(float x) {
    return 0.5f * x * (1.0f + erff(x * 0.70710678118654752440f));
}

__device__ __forceinline__ uint32_t f2tf32(float x) {
    uint32_t r;
    asm("cvt.rna.tf32.f32 %0, %1;" : "=r"(r) : "f"(x));
    return r;
}

__device__ __forceinline__ void cp16(void* dst_smem, const void* src_gmem) {
    uint32_t d = (uint32_t)__cvta_generic_to_shared(dst_smem);
    asm volatile("cp.async.cg.shared.global [%0], [%1], 16;" :: "r"(d), "l"(src_gmem));
}
__device__ __forceinline__ void cp_commit() {
    asm volatile("cp.async.commit_group;");
}
__device__ __forceinline__ void cp_wait1() {
    asm volatile("cp.async.wait_group 1;");
}

// D += A(m16k8,row) * B(k8n8,col)   tf32
__device__ __forceinline__ void mma8(float* c, const uint32_t* a, const uint32_t* b) {
    asm volatile("mma.sync.aligned.m16n8k8.row.col.f32.tf32.tf32.f32 "
                 "{%0,%1,%2,%3}, {%4,%5,%6,%7}, {%8,%9}, {%0,%1,%2,%3};"
                 : "+f"(c[0]), "+f"(c[1]), "+f"(c[2]), "+f"(c[3])
                 : "r"(a[0]), "r"(a[1]), "r"(a[2]), "r"(a[3]),
                   "r"(b[0]), "r"(b[1]));
}

// D += A(m16k16,row,f16) * B(k16n8,col,f16), fp32 accum
__device__ __forceinline__ void mma16h(float* c, const uint32_t* a, const uint32_t* b) {
    asm volatile("mma.sync.aligned.m16n8k16.row.col.f32.f16.f16.f32 "
                 "{%0,%1,%2,%3}, {%4,%5,%6,%7}, {%8,%9}, {%0,%1,%2,%3};"
                 : "+f"(c[0]), "+f"(c[1]), "+f"(c[2]), "+f"(c[3])
                 : "r"(a[0]), "r"(a[1]), "r"(a[2]), "r"(a[3]),
                   "r"(b[0]), "r"(b[1]));
}

// ------- weight transpose+convert: Wt[n][k] = (half)W[k][n] ------------------
__global__ __launch_bounds__(256) void wt_kernel(const float* __restrict__ W,
                                                 __half* __restrict__ Wt,
                                                 int K, int N) {
    __shared__ float tile[32][33];
    int k0 = blockIdx.x * 32, n0 = blockIdx.y * 32;
    int t = threadIdx.x;
    int i = t & 31, j0 = t >> 5;
#pragma unroll
    for (int jj = 0; jj < 32; jj += 8)
        tile[j0 + jj][i] = W[(size_t)(k0 + j0 + jj) * N + n0 + i];
    __syncthreads();
#pragma unroll
    for (int jj = 0; jj < 32; jj += 8)
        Wt[(size_t)(n0 + j0 + jj) * K + k0 + i] = __float2half_rn(tile[i][j0 + jj]);
}

// ---------------- LayerNorm: fp32 in, fp16 out; one block per row -------------
__global__ __launch_bounds__(256) void ln_kernel(const float* __restrict__ x,
                                                 const float* __restrict__ w,
                                                 const float* __restrict__ b,
                                                 __half* __restrict__ out) {
    __shared__ float sh1[8], sh2[8];
    int row = blockIdx.x;
    int t = threadIdx.x;
    const float* xr = x + (size_t)row * kD;
    float v[3];
    float s = 0.f, s2 = 0.f;
#pragma unroll
    for (int i = 0; i < 3; i++) {
        v[i] = xr[t + i * 256];
        s  += v[i];
        s2 += v[i] * v[i];
    }
#pragma unroll
    for (int o = 16; o; o >>= 1) {
        s  += __shfl_xor_sync(0xffffffffu, s, o);
        s2 += __shfl_xor_sync(0xffffffffu, s2, o);
    }
    if ((t & 31) == 0) { sh1[t >> 5] = s; sh2[t >> 5] = s2; }
    __syncthreads();
    s = sh1[t & 7]; s2 = sh2[t & 7];
#pragma unroll
    for (int o = 4; o; o >>= 1) {
        s  += __shfl_xor_sync(0xffffffffu, s, o);
        s2 += __shfl_xor_sync(0xffffffffu, s2, o);
    }
    float mu   = s * (1.0f / kD);
    float var  = fmaxf(s2 * (1.0f / kD) - mu * mu, 0.f);
    float rstd = rsqrtf(var + 1e-5f);
    __half* orow = out + (size_t)row * kD;
#pragma unroll
    for (int i = 0; i < 3; i++) {
        int c = t + i * 256;
        orow[c] = __float2half_rn((v[i] - mu) * rstd * w[c] + b[c]);
    }
}

// ------- FP16 GEMM (NT): C[M,N] = A[M,K] @ Bt[N,K]^T + bias (+gelu)(+res) ----
// 128x128 block, 8 warps (4m x 2n), K-step 32, 3-stage cp.async.
// A and Bt both k-contiguous fp16; fp32 accumulate; C fp32 or fp16 by flag.
__global__ __launch_bounds__(256) void gemm_f16_nt(
        const __half* __restrict__ A, const __half* __restrict__ Bt,
        const float* __restrict__ bias, const float* __restrict__ res,
        void* __restrict__ Cout, int M, int N, int K, int act, int outHalf) {
    extern __shared__ __half hsm[];
    __half* AsBuf = hsm;                        // [3][128*40]
    __half* BsBuf = hsm + 3 * 128 * 40;         // [3][128*40]
#define HAS(s, r, c) AsBuf[(s) * 5120 + (r) * 40 + (c)]
#define HBS(s, r, c) BsBuf[(s) * 5120 + (r) * 40 + (c)]
    int tid = threadIdx.x, lane = tid & 31, warp = tid >> 5;
    int g = lane >> 2, tg = lane & 3;
    int wm = (warp >> 1) * 32, wn = (warp & 1) * 64;
    int row0 = blockIdx.y * 128, col0 = blockIdx.x * 128;
    int ra = tid >> 1, cha = (tid & 1) * 16;     // loader: 128 rows, 2 thr/row
    const __half* Ap = A  + (size_t)(row0 + ra) * K + cha;
    const __half* Bp = Bt + (size_t)(col0 + ra) * K + cha;
    float acc[2][8][4] = {};

    auto issue = [&](int k0, int s) {
        if (k0 < K) {
            cp16(&HAS(s, ra, cha),     Ap + k0);
            cp16(&HAS(s, ra, cha + 8), Ap + k0 + 8);
            cp16(&HBS(s, ra, cha),     Bp + k0);
            cp16(&HBS(s, ra, cha + 8), Bp + k0 + 8);
        }
        cp_commit();
    };
    issue(0, 0);
    issue(32, 1);
    int s = 0;
    for (int k0 = 0; k0 < K; k0 += 32) {
        cp_wait1();
        __syncthreads();
        int s2n = s + 2 >= 3 ? s - 1 : s + 2;
        issue(k0 + 64, s2n);
#pragma unroll
        for (int k16 = 0; k16 < 32; k16 += 16) {
            uint32_t af[2][4], bf[8][2];
#pragma unroll
            for (int mi = 0; mi < 2; mi++) {
                int r = wm + mi * 16 + g;
                af[mi][0] = *(const uint32_t*)&HAS(s, r,     k16 + 2 * tg);
                af[mi][1] = *(const uint32_t*)&HAS(s, r + 8, k16 + 2 * tg);
                af[mi][2] = *(const uint32_t*)&HAS(s, r,     k16 + 2 * tg + 8);
                af[mi][3] = *(const uint32_t*)&HAS(s, r + 8, k16 + 2 * tg + 8);
            }
#pragma unroll
            for (int nj = 0; nj < 8; nj++) {
                int n = wn + nj * 8 + g;
                bf[nj][0] = *(const uint32_t*)&HBS(s, n, k16 + 2 * tg);
                bf[nj][1] = *(const uint32_t*)&HBS(s, n, k16 + 2 * tg + 8);
            }
#pragma unroll
            for (int mi = 0; mi < 2; mi++)
#pragma unroll
                for (int nj = 0; nj < 8; nj++)
                    mma16h(acc[mi][nj], af[mi], bf[nj]);
        }
        s = s + 1 >= 3 ? 0 : s + 1;
    }
#undef HAS
#undef HBS
#pragma unroll
    for (int mi = 0; mi < 2; mi++) {
#pragma unroll
        for (int nj = 0; nj < 8; nj++) {
            int r0 = row0 + wm + mi * 16 + g;
            int c = col0 + wn + nj * 8 + tg * 2;
            float b0 = bias[c], b1 = bias[c + 1];
            float o00 = acc[mi][nj][0] + b0, o01 = acc[mi][nj][1] + b1;
            float o10 = acc[mi][nj][2] + b0, o11 = acc[mi][nj][3] + b1;
            if (act) {
                o00 = gelu_exact(o00); o01 = gelu_exact(o01);
                o10 = gelu_exact(o10); o11 = gelu_exact(o11);
            }
            if (res) {
                o00 += res[(size_t)r0 * N + c];       o01 += res[(size_t)r0 * N + c + 1];
                o10 += res[(size_t)(r0 + 8) * N + c]; o11 += res[(size_t)(r0 + 8) * N + c + 1];
            }
            if (outHalf) {
                __half* C = (__half*)Cout;
                *(__half2*)&C[(size_t)r0 * N + c]       = __floats2half2_rn(o00, o01);
                *(__half2*)&C[(size_t)(r0 + 8) * N + c] = __floats2half2_rn(o10, o11);
            } else {
                float* C = (float*)Cout;
                *(float2*)&C[(size_t)r0 * N + c]       = make_float2(o00, o01);
                *(float2*)&C[(size_t)(r0 + 8) * N + c] = make_float2(o10, o11);
            }
        }
    }
}

// ------- scores S = scale * Q @ K^T (NT), tf32 compute, fp16 store ------------
__global__ __launch_bounds__(256) void score_tf32(const float* __restrict__ qkv,
                                                  __half* __restrict__ S) {
    __shared__ uint32_t As[128][20];
    __shared__ uint32_t Bs[128][20];
    int bh = blockIdx.z, b = bh / kH, h = bh % kH;
    const float* qb = qkv + (size_t)b * kN * kQD + h * kHD;
    const float* kb = qb + kD;
    int tid = threadIdx.x, lane = tid & 31, warp = tid >> 5;
    int g = lane >> 2, tg = lane & 3;
    int wm = (warp >> 1) * 32, wn = (warp & 1) * 64;
    int n0 = blockIdx.y * 128, m0 = blockIdx.x * 128;
    int ra = tid >> 2, ca = (tid & 3) * 4;
    const float* Qp0 = qb + (size_t)(n0 + ra) * kQD + ca;
    const float* Qp1 = Qp0 + (size_t)64 * kQD;
    const float* Kp0 = kb + (size_t)(m0 + ra) * kQD + ca;
    const float* Kp1 = Kp0 + (size_t)64 * kQD;
    float acc[2][8][4] = {};
    float4 q0 = *(const float4*)Qp0, q1 = *(const float4*)Qp1;
    float4 v0 = *(const float4*)Kp0, v1 = *(const float4*)Kp1;
    for (int k0 = 0; k0 < kHD; k0 += 16) {
        As[ra][ca + 0] = f2tf32(q0.x); As[ra][ca + 1] = f2tf32(q0.y);
        As[ra][ca + 2] = f2tf32(q0.z); As[ra][ca + 3] = f2tf32(q0.w);
        As[ra + 64][ca + 0] = f2tf32(q1.x); As[ra + 64][ca + 1] = f2tf32(q1.y);
        As[ra + 64][ca + 2] = f2tf32(q1.z); As[ra + 64][ca + 3] = f2tf32(q1.w);
        Bs[ra][ca + 0] = f2tf32(v0.x); Bs[ra][ca + 1] = f2tf32(v0.y);
        Bs[ra][ca + 2] = f2tf32(v0.z); Bs[ra][ca + 3] = f2tf32(v0.w);
        Bs[ra + 64][ca + 0] = f2tf32(v1.x); Bs[ra + 64][ca + 1] = f2tf32(v1.y);
        Bs[ra + 64][ca + 2] = f2tf32(v1.z); Bs[ra + 64][ca + 3] = f2tf32(v1.w);
        __syncthreads();
        if (k0 + 16 < kHD) {
            q0 = *(const float4*)(Qp0 + k0 + 16);
            q1 = *(const float4*)(Qp1 + k0 + 16);
            v0 = *(const float4*)(Kp0 + k0 + 16);
            v1 = *(const float4*)(Kp1 + k0 + 16);
        }
#pragma unroll
        for (int k8 = 0; k8 < 16; k8 += 8) {
            uint32_t af[2][4], bf[8][2];
#pragma unroll
            for (int mi = 0; mi < 2; mi++) {
                int r = wm + mi * 16 + g;
                af[mi][0] = As[r][k8 + tg];
                af[mi][1] = As[r + 8][k8 + tg];
                af[mi][2] = As[r][k8 + tg + 4];
                af[mi][3] = As[r + 8][k8 + tg + 4];
            }
#pragma unroll
            for (int nj = 0; nj < 8; nj++) {
                int n = wn + nj * 8 + g;
                bf[nj][0] = Bs[n][k8 + tg];
                bf[nj][1] = Bs[n][k8 + tg + 4];
            }
#pragma unroll
            for (int mi = 0; mi < 2; mi++)
#pragma unroll
                for (int nj = 0; nj < 8; nj++)
                    mma8(acc[mi][nj], af[mi], bf[nj]);
        }
        __syncthreads();
    }
    __half* Sb = S + (size_t)bh * kN * kN;
#pragma unroll
    for (int mi = 0; mi < 2; mi++) {
#pragma unroll
        for (int nj = 0; nj < 8; nj++) {
            int r0 = n0 + wm + mi * 16 + g;
            int c = m0 + wn + nj * 8 + tg * 2;
            *(__half2*)&Sb[(size_t)r0 * kN + c] =
                __floats2half2_rn(acc[mi][nj][0] * 0.125f, acc[mi][nj][1] * 0.125f);
            *(__half2*)&Sb[(size_t)(r0 + 8) * kN + c] =
                __floats2half2_rn(acc[mi][nj][2] * 0.125f, acc[mi][nj][3] * 0.125f);
        }
    }
}

// ---------------- G = gw @ gw^T (NT), tf32, K=64 padded ----------------
__global__ __launch_bounds__(256) void gmat_tf32(const float* __restrict__ gw,
                                                 float* __restrict__ G) {
    __shared__ uint32_t As[128][20];
    __shared__ uint32_t Bs[128][20];
    int bh = blockIdx.z;
    const float* gb = gw + (size_t)bh * kN * 64;
    int tid = threadIdx.x, lane = tid & 31, warp = tid >> 5;
    int g = lane >> 2, tg = lane & 3;
    int wm = (warp >> 1) * 32, wn = (warp & 1) * 64;
    int n0 = blockIdx.y * 128, m0 = blockIdx.x * 128;
    int ra = tid >> 2, ca = (tid & 3) * 4;
    const float* Ap0 = gb + (size_t)(n0 + ra) * 64 + ca;
    const float* Ap1 = Ap0 + (size_t)64 * 64;
    const float* Bp0 = gb + (size_t)(m0 + ra) * 64 + ca;
    const float* Bp1 = Bp0 + (size_t)64 * 64;
    float acc[2][8][4] = {};
    float4 a0 = *(const float4*)Ap0, a1 = *(const float4*)Ap1;
    float4 b0 = *(const float4*)Bp0, b1 = *(const float4*)Bp1;
    for (int k0 = 0; k0 < 64; k0 += 16) {
        As[ra][ca + 0] = f2tf32(a0.x); As[ra][ca + 1] = f2tf32(a0.y);
        As[ra][ca + 2] = f2tf32(a0.z); As[ra][ca + 3] = f2tf32(a0.w);
        As[ra + 64][ca + 0] = f2tf32(a1.x); As[ra + 64][ca + 1] = f2tf32(a1.y);
        As[ra + 64][ca + 2] = f2tf32(a1.z); As[ra + 64][ca + 3] = f2tf32(a1.w);
        Bs[ra][ca + 0] = f2tf32(b0.x); Bs[ra][ca + 1] = f2tf32(b0.y);
        Bs[ra][ca + 2] = f2tf32(b0.z); Bs[ra][ca + 3] = f2tf32(b0.w);
        Bs[ra + 64][ca + 0] = f2tf32(b1.x); Bs[ra + 64][ca + 1] = f2tf32(b1.y);
        Bs[ra + 64][ca + 2] = f2tf32(b1.z); Bs[ra + 64][ca + 3] = f2tf32(b1.w);
        __syncthreads();
        if (k0 + 16 < 64) {
            a0 = *(const float4*)(Ap0 + k0 + 16);
            a1 = *(const float4*)(Ap1 + k0 + 16);
            b0 = *(const float4*)(Bp0 + k0 + 16);
            b1 = *(const float4*)(Bp1 + k0 + 16);
        }
#pragma unroll
        for (int k8 = 0; k8 < 16; k8 += 8) {
            uint32_t af[2][4], bf[8][2];
#pragma unroll
            for (int mi = 0; mi < 2; mi++) {
                int r = wm + mi * 16 + g;
                af[mi][0] = As[r][k8 + tg];
                af[mi][1] = As[r + 8][k8 + tg];
                af[mi][2] = As[r][k8 + tg + 4];
                af[mi][3] = As[r + 8][k8 + tg + 4];
            }
#pragma unroll
            for (int nj = 0; nj < 8; nj++) {
                int n = wn + nj * 8 + g;
                bf[nj][0] = Bs[n][k8 + tg];
                bf[nj][1] = Bs[n][k8 + tg + 4];
            }
#pragma unroll
            for (int mi = 0; mi < 2; mi++)
#pragma unroll
                for (int nj = 0; nj < 8; nj++)
                    mma8(acc[mi][nj], af[mi], bf[nj]);
        }
        __syncthreads();
    }
    float* Gb = G + (size_t)bh * kN * kN;
#pragma unroll
    for (int mi = 0; mi < 2; mi++) {
#pragma unroll
        for (int nj = 0; nj < 8; nj++) {
            int r0 = n0 + wm + mi * 16 + g;
            int c = m0 + wn + nj * 8 + tg * 2;
            *(float2*)&Gb[(size_t)r0 * kN + c] =
                make_float2(acc[mi][nj][0], acc[mi][nj][1]);
            *(float2*)&Gb[(size_t)(r0 + 8) * kN + c] =
                make_float2(acc[mi][nj][2], acc[mi][nj][3]);
        }
    }
}

// ------- per-row: P = softmax(S*G); A = (1-a)P + a*G  (fp16 S in/out) --------
__global__ __launch_bounds__(256) void rowmix_kernel(const float* __restrict__ alpha,
                                                     __half* __restrict__ S,
                                                     const float* __restrict__ G) {
    __shared__ float sh1[8];
    int gr = blockIdx.x;                 // bh*N + n
    int h = (gr >> 10) % kH;
    size_t off = (size_t)gr * kN;
    int t = threadIdx.x;
    float a = 1.f / (1.f + __expf(-alpha[h]));
    __half2* Sh = (__half2*)(S + off);
    __half2 p0 = Sh[t * 2], p1 = Sh[t * 2 + 1];
    float2 f0 = __half22float2(p0), f1 = __half22float2(p1);
    float4 gv = *(const float4*)&G[off + t * 4];
    float tv[4] = { f0.x * gv.x, f0.y * gv.y, f1.x * gv.z, f1.y * gv.w };
    float mx = fmaxf(fmaxf(tv[0], tv[1]), fmaxf(tv[2], tv[3]));
    for (int o = 16; o; o >>= 1) mx = fmaxf(mx, __shfl_xor_sync(0xffffffffu, mx, o));
    if ((t & 31) == 0) sh1[t >> 5] = mx;
    __syncthreads();
    mx = sh1[t & 7];
    for (int o = 4; o; o >>= 1) mx = fmaxf(mx, __shfl_xor_sync(0xffffffffu, mx, o));
    __syncthreads();
    float e[4], sum = 0.f;
#pragma unroll
    for (int i = 0; i < 4; i++) { e[i] = __expf(tv[i] - mx); sum += e[i]; }
    for (int o = 16; o; o >>= 1) sum += __shfl_xor_sync(0xffffffffu, sum, o);
    if ((t & 31) == 0) sh1[t >> 5] = sum;
    __syncthreads();
    sum = sh1[t & 7];
    for (int o = 4; o; o >>= 1) sum += __shfl_xor_sync(0xffffffffu, sum, o);
    float isum = (1.f - a) / sum;
    Sh[t * 2]     = __floats2half2_rn(e[0] * isum + a * gv.x, e[1] * isum + a * gv.y);
    Sh[t * 2 + 1] = __floats2half2_rn(e[2] * isum + a * gv.z, e[3] * isum + a * gv.w);
}

// ------- column sums over n (axis=2), fp16 A, stores 1/(sum+1e-8) -------
__global__ __launch_bounds__(256) void colsum_kernel(const __half* __restrict__ Sa,
                                                     float* __restrict__ inv) {
    int idx = blockIdx.x * 256 + threadIdx.x;   // bh*N + m
    int bh = idx >> 10, m = idx & 1023;
    const __half* p = Sa + (size_t)bh * kN * kN + m;
    float s0 = 0.f, s1 = 0.f, s2 = 0.f, s3 = 0.f;
    float s4 = 0.f, s5 = 0.f, s6 = 0.f, s7 = 0.f;
#pragma unroll 4
    for (int n = 0; n < kN; n += 8) {
        s0 += __half2float(p[(size_t)(n + 0) * kN]);
        s1 += __half2float(p[(size_t)(n + 1) * kN]);
        s2 += __half2float(p[(size_t)(n + 2) * kN]);
        s3 += __half2float(p[(size_t)(n + 3) * kN]);
        s4 += __half2float(p[(size_t)(n + 4) * kN]);
        s5 += __half2float(p[(size_t)(n + 5) * kN]);
        s6 += __half2float(p[(size_t)(n + 6) * kN]);
        s7 += __half2float(p[(size_t)(n + 7) * kN]);
    }
    float s = ((s0 + s1) + (s2 + s3)) + ((s4 + s5) + (s6 + s7));
    inv[idx] = 1.f / (s + 1e-8f);
}

// ------- vs[bh][d][k] = V[b,k,h,d] * inv[bh,k]   (transposed, fp16) ----------
__global__ __launch_bounds__(256) void vscale_t_kernel(const float* __restrict__ qkv,
                                                       const float* __restrict__ inv,
                                                       __half* __restrict__ vs) {
    __shared__ __half tile[64][72];   // [d][k], padded
    int bh = blockIdx.y, k0 = blockIdx.x * 64;
    int b = bh / kH, h = bh % kH;
    int t = threadIdx.x;
    for (int i = t; i < 64 * 16; i += 256) {      // 64 k-rows x 16 float4
        int kk = i >> 4, d4 = (i & 15) * 4;
        float iv = inv[bh * kN + k0 + kk];
        float4 v = *(const float4*)(qkv + (size_t)(b * kN + k0 + kk) * kQD
                                    + 2 * kD + h * kHD + d4);
        tile[d4 + 0][kk] = __float2half_rn(v.x * iv);
        tile[d4 + 1][kk] = __float2half_rn(v.y * iv);
        tile[d4 + 2][kk] = __float2half_rn(v.z * iv);
        tile[d4 + 3][kk] = __float2half_rn(v.w * iv);
    }
    __syncthreads();
    for (int i = t; i < 64 * 8; i += 256) {       // 512 x 16B chunks
        int d = i >> 3, ch = (i & 7) * 8;
        *(uint4*)(vs + ((size_t)bh * kHD + d) * kN + k0 + ch) = *(uint4*)&tile[d][ch];
    }
}

// ------- out = A @ Vs (fp16 m16n8k16, fp32 accum), ctx fp16 out ---------------
__global__ __launch_bounds__(256) void av_f16(const __half* __restrict__ Sa,
                                              const __half* __restrict__ vs,
                                              __half* __restrict__ ctx) {
    __shared__ __align__(16) __half As[3][128][24];
    __shared__ __align__(16) __half Bs[3][64][24];
    int bh = blockIdx.z, b = bh / kH, h = bh % kH;
    const __half* Ab = Sa + (size_t)bh * kN * kN;
    const __half* vb = vs + (size_t)bh * kHD * kN;
    int tid = threadIdx.x, lane = tid & 31, warp = tid >> 5;
    int g = lane >> 2, tg = lane & 3;
    int wm = (warp >> 1) * 32, wn = (warp & 1) * 32;
    int row0 = blockIdx.y * 128;
    int ra = tid >> 1, cha = (tid & 1) * 8;
    int db = (tid & 127) >> 1, chb = (tid & 1) * 8;
    const __half* Ap = Ab + (size_t)(row0 + ra) * kN + cha;
    const __half* Vp = vb + (size_t)db * kN + chb;
    float acc[2][4][4] = {};
    auto issue = [&](int k0, int s) {
        if (k0 < kN) {
            cp16(&As[s][ra][cha], Ap + k0);
            if (tid < 128) cp16(&Bs[s][db][chb], Vp + k0);
        }
        cp_commit();
    };
    issue(0, 0);
    issue(16, 1);
    int s = 0;
    for (int k0 = 0; k0 < kN; k0 += 16) {
        cp_wait1();
        __syncthreads();
        int s2n = s + 2 >= 3 ? s - 1 : s + 2;
        issue(k0 + 32, s2n);
        uint32_t af[2][4], bf[4][2];
#pragma unroll
        for (int mi = 0; mi < 2; mi++) {
            int r = wm + mi * 16 + g;
            af[mi][0] = *(const uint32_t*)&As[s][r][2 * tg];
            af[mi][1] = *(const uint32_t*)&As[s][r + 8][2 * tg];
            af[mi][2] = *(const uint32_t*)&As[s][r][2 * tg + 8];
            af[mi][3] = *(const uint32_t*)&As[s][r + 8][2 * tg + 8];
        }
#pragma unroll
        for (int nj = 0; nj < 4; nj++) {
            int n = wn + nj * 8 + g;
            bf[nj][0] = *(const uint32_t*)&Bs[s][n][2 * tg];
            bf[nj][1] = *(const uint32_t*)&Bs[s][n][2 * tg + 8];
        }
#pragma unroll
        for (int mi = 0; mi < 2; mi++)
#pragma unroll
            for (int nj = 0; nj < 4; nj++)
                mma16h(acc[mi][nj], af[mi], bf[nj]);
        s = s + 1 >= 3 ? 0 : s + 1;
    }
#pragma unroll
    for (int mi = 0; mi < 2; mi++) {
#pragma unroll
        for (int nj = 0; nj < 4; nj++) {
            int tok0 = b * kN + row0 + wm + mi * 16 + g;
            int c = h * kHD + wn + nj * 8 + tg * 2;
            *(__half2*)&ctx[(size_t)tok0 * kD + c] =
                __floats2half2_rn(acc[mi][nj][0], acc[mi][nj][1]);
            *(__half2*)&ctx[(size_t)(tok0 + 8) * kD + c] =
                __floats2half2_rn(acc[mi][nj][2], acc[mi][nj][3]);
        }
    }
}

// ---- group weights: gw = softmax(gelu(V @ gp^T)) padded to 64 ----
__global__ __launch_bounds__(256) void gw_kernel(const float* __restrict__ qkv,
                                                 const float* __restrict__ gp_w,
                                                 float* __restrict__ gw) {
    __shared__ __align__(16) float gps[kGP][68];
    __shared__ __align__(16) float Vs[64][68];
    int bh = blockIdx.y;
    int b = bh / kH, h = bh % kH;
    int n0 = blockIdx.x * 64;
    int tid = threadIdx.x;
    const float* gph = gp_w + (size_t)h * kGP * kHD;
    for (int i = tid; i < kGP * 16; i += 256) {
        int r = i >> 4, c4 = (i & 15) * 4;
        *(float4*)&gps[r][c4] = *(const float4*)(gph + r * kHD + c4);
    }
    const float* vb = qkv + (size_t)(b * kN + n0) * kQD + 2 * kD + h * kHD;
    for (int i = tid; i < 64 * 16; i += 256) {
        int r = i >> 4, c4 = (i & 15) * 4;
        *(float4*)&Vs[r][c4] = *(const float4*)(vb + (size_t)r * kQD + c4);
    }
    __syncthreads();
    int r = tid >> 2;
    int c0 = tid & 3;
    float val[13];
    float mx = -1e30f;
#pragma unroll
    for (int j = 0; j < 13; j++) {
        int c = c0 + 4 * j;
        float acc = 0.f;
        if (c < kGP) {
#pragma unroll
            for (int d = 0; d < kHD; d += 4) {
                float4 vv = *(const float4*)&Vs[r][d];
                float4 gg = *(const float4*)&gps[c][d];
                acc += vv.x * gg.x + vv.y * gg.y + vv.z * gg.z + vv.w * gg.w;
            }
            acc = gelu_exact(acc);
            mx = fmaxf(mx, acc);
        }
        val[j] = acc;
    }
    mx = fmaxf(mx, __shfl_xor_sync(0xffffffffu, mx, 1));
    mx = fmaxf(mx, __shfl_xor_sync(0xffffffffu, mx, 2));
    float sum = 0.f;
#pragma unroll
    for (int j = 0; j < 13; j++) {
        int c = c0 + 4 * j;
        val[j] = (c < kGP) ? __expf(val[j] - mx) : 0.f;
        sum += val[j];
    }
    sum += __shfl_xor_sync(0xffffffffu, sum, 1);
    sum += __shfl_xor_sync(0xffffffffu, sum, 2);
    float is = 1.f / sum;
    float* grow = gw + (size_t)(bh * kN + n0 + r) * 64;
#pragma unroll
    for (int j = 0; j < 16; j++) {
        int c = c0 + 4 * j;
        if (c < 64) grow[c] = (j < 13 && c < kGP) ? val[j] * is : 0.f;
    }
}

// ---------------- launch ----------------
extern "C" void kernel_launch(void* const* d_in, const int* in_sizes, int n_in,
                              void* d_out, int out_size) {
    const float* x      = (const float*)d_in[0];
    const float* ln1_w  = (const float*)d_in[1];
    const float* ln1_b  = (const float*)d_in[2];
    const float* qkv_w  = (const float*)d_in[3];
    const float* qkv_b  = (const float*)d_in[4];
    const float* proj_w = (const float*)d_in[5];
    const float* proj_b = (const float*)d_in[6];
    const float* gp_w   = (const float*)d_in[7];
    const float* alpha  = (const float*)d_in[8];
    const float* ln2_w  = (const float*)d_in[9];
    const float* ln2_b  = (const float*)d_in[10];
    const float* ff1_w  = (const float*)d_in[11];
    const float* ff1_b  = (const float*)d_in[12];
    const float* ff2_w  = (const float*)d_in[13];
    const float* ff2_b  = (const float*)d_in[14];
    float* out = (float*)d_out;

    float *qkv, *G, *gw, *inv, *y;
    __half *xn, *S, *vs, *ctx, *yn, *hdn;
    __half *qkvwt, *projwt, *ff1wt, *ff2wt;
    cudaGetSymbolAddress((void**)&xn,  g_xn);
    cudaGetSymbolAddress((void**)&qkv, g_qkv);
    cudaGetSymbolAddress((void**)&S,   g_S);
    cudaGetSymbolAddress((void**)&G,   g_G);
    cudaGetSymbolAddress((void**)&gw,  g_gw);
    cudaGetSymbolAddress((void**)&inv, g_inv);
    cudaGetSymbolAddress((void**)&vs,  g_vs);
    cudaGetSymbolAddress((void**)&ctx, g_ctx);
    cudaGetSymbolAddress((void**)&y,   g_y);
    cudaGetSymbolAddress((void**)&yn,  g_yn);
    cudaGetSymbolAddress((void**)&hdn, g_hdn);
    cudaGetSymbolAddress((void**)&qkvwt,  g_qkvwt);
    cudaGetSymbolAddress((void**)&projwt, g_projwt);
    cudaGetSymbolAddress((void**)&ff1wt,  g_ff1wt);
    cudaGetSymbolAddress((void**)&ff2wt,  g_ff2wt);

    cudaFuncSetAttribute(gemm_f16_nt,
                         cudaFuncAttributeMaxDynamicSharedMemorySize, kGemmSmemH);

    // weight transposes (fp32 -> fp16, [K][N] -> [N][K])
    wt_kernel<<<dim3(kD / 32, kQD / 32), 256>>>(qkv_w, qkvwt, kD, kQD);
    wt_kernel<<<dim3(kD / 32, kD / 32), 256>>>(proj_w, projwt, kD, kD);
    wt_kernel<<<dim3(kD / 32, kMLP / 32), 256>>>(ff1_w, ff1wt, kD, kMLP);
    wt_kernel<<<dim3(kMLP / 32, kD / 32), 256>>>(ff2_w, ff2wt, kMLP, kD);

    // attention branch
    ln_kernel<<<kT, 256>>>(x, ln1_w, ln1_b, xn);
    gemm_f16_nt<<<dim3(kQD / 128, kT / 128), 256, kGemmSmemH>>>(
        xn, qkvwt, qkv_b, nullptr, qkv, kT, kQD, kD, 0, 0);
    score_tf32<<<dim3(8, 8, kBH), 256>>>(qkv, S);
    gw_kernel<<<dim3(kN / 64, kBH), 256>>>(qkv, gp_w, gw);
    gmat_tf32<<<dim3(8, 8, kBH), 256>>>(gw, G);
    rowmix_kernel<<<kBH * kN, 256>>>(alpha, S, G);
    colsum_kernel<<<kBH * kN / 256, 256>>>(S, inv);
    vscale_t_kernel<<<dim3(kN / 64, kBH), 256>>>(qkv, inv, vs);
    av_f16<<<dim3(1, 8, kBH), 256>>>(S, vs, ctx);
    gemm_f16_nt<<<dim3(kD / 128, kT / 128), 256, kGemmSmemH>>>(
        ctx, projwt, proj_b, x, y, kT, kD, kD, 0, 0);
    // FFN branch
    ln_kernel<<<kT, 256>>>(y, ln2_w, ln2_b, yn);
    gemm_f16_nt<<<dim3(kMLP / 128, kT / 128), 256, kGemmSmemH>>>(
        yn, ff1wt, ff1_b, nullptr, hdn, kT, kMLP, kD, 1, 1);
    gemm_f16_nt<<<dim3(kD / 128, kT / 128), 256, kGemmSmemH>>>(
        hdn, ff2wt, ff2_b, y, out, kT, kD, kMLP, 0, 0);
}

// round 14
// speedup vs baseline: 1.6356x; 1.0905x over previous
#include <cuda_runtime.h>
#include <cuda_fp16.h>
#include <math.h>
#include <stdint.h>

// ---------------- problem constants ----------------
namespace {
constexpr int kB  = 4;
constexpr int kN  = 1024;
constexpr int kD  = 768;
constexpr int kH  = 12;
constexpr int kHD = 64;
constexpr int kGP = 49;
constexpr int kMLP = 3072;
constexpr int kT  = kB * kN;     // 4096 tokens
constexpr int kBH = kB * kH;     // 48 batched heads
constexpr int kQD = 3 * kD;      // 2304
constexpr int kGemmSmemH = 3 * (128 * 40 + 128 * 40) * 2;
}

// ---------------- scratch (device globals: no allocation allowed) ----------------
__device__ __half g_xn  [kT * kD];                // fp16 LN1 output
__device__ __half g_qkvh[kT * kQD];               // fp16 qkv
__device__ __half g_S   [(size_t)kBH * kN * kN];  // fp16 scores, later mixed attn A
__device__ __half g_G   [(size_t)kBH * kN * kN];  // fp16 gw @ gw^T
__device__ __half g_gw  [kBH * kN * 64];          // fp16 softmaxed group weights (pad 49->64)
__device__ float  g_inv [kBH * kN];               // 1/(colsum+eps)
__device__ __half g_vs  [(size_t)kBH * kHD * kN]; // inv-scaled V, TRANSPOSED [bh][d][k]
__device__ __half g_ctx [kT * kD];                // merged-head attention output (fp16)
__device__ float  g_y   [kT * kD];                // after proj residual (fp32)
__device__ __half g_yn  [kT * kD];                // fp16 LN2 output
__device__ __half g_hdn [kT * kMLP];              // fp16 gelu(ff1)
// transposed fp16 weights
__device__ __half g_qkvwt[kQD * kD];
__device__ __half g_projwt[kD * kD];
__device__ __half g_ff1wt [kMLP * kD];
__device__ __half g_ff2wt [kD * kMLP];

__device__ __forceinline__ float gelu_exact(float x) {
    return 0.5f * x * (1.0f + erff(x * 0.70710678118654752440f));
}

__device__ __forceinline__ void cp16(void* dst_smem, const void* src_gmem) {
    uint32_t d = (uint32_t)__cvta_generic_to_shared(dst_smem);
    asm volatile("cp.async.cg.shared.global [%0], [%1], 16;" :: "r"(d), "l"(src_gmem));
}
__device__ __forceinline__ void cp_commit() {
    asm volatile("cp.async.commit_group;");
}
__device__ __forceinline__ void cp_wait0() {
    asm volatile("cp.async.wait_group 0;");
}
__device__ __forceinline__ void cp_wait1() {
    asm volatile("cp.async.wait_group 1;");
}

// D += A(m16k16,row,f16) * B(k16n8,col,f16), fp32 accum
__device__ __forceinline__ void mma16h(float* c, const uint32_t* a, const uint32_t* b) {
    asm volatile("mma.sync.aligned.m16n8k16.row.col.f32.f16.f16.f32 "
                 "{%0,%1,%2,%3}, {%4,%5,%6,%7}, {%8,%9}, {%0,%1,%2,%3};"
                 : "+f"(c[0]), "+f"(c[1]), "+f"(c[2]), "+f"(c[3])
                 : "r"(a[0]), "r"(a[1]), "r"(a[2]), "r"(a[3]),
                   "r"(b[0]), "r"(b[1]));
}

// ------- weight transpose+convert: Wt[n][k] = (half)W[k][n] ------------------
__global__ __launch_bounds__(256) void wt_kernel(const float* __restrict__ W,
                                                 __half* __restrict__ Wt,
                                                 int K, int N) {
    __shared__ float tile[32][33];
    int k0 = blockIdx.x * 32, n0 = blockIdx.y * 32;
    int t = threadIdx.x;
    int i = t & 31, j0 = t >> 5;
#pragma unroll
    for (int jj = 0; jj < 32; jj += 8)
        tile[j0 + jj][i] = W[(size_t)(k0 + j0 + jj) * N + n0 + i];
    __syncthreads();
#pragma unroll
    for (int jj = 0; jj < 32; jj += 8)
        Wt[(size_t)(n0 + j0 + jj) * K + k0 + i] = __float2half_rn(tile[i][j0 + jj]);
}

// ---------------- LayerNorm: fp32 in, fp16 out; one block per row -------------
__global__ __launch_bounds__(256) void ln_kernel(const float* __restrict__ x,
                                                 const float* __restrict__ w,
                                                 const float* __restrict__ b,
                                                 __half* __restrict__ out) {
    __shared__ float sh1[8], sh2[8];
    int row = blockIdx.x;
    int t = threadIdx.x;
    const float* xr = x + (size_t)row * kD;
    float v[3];
    float s = 0.f, s2 = 0.f;
#pragma unroll
    for (int i = 0; i < 3; i++) {
        v[i] = xr[t + i * 256];
        s  += v[i];
        s2 += v[i] * v[i];
    }
#pragma unroll
    for (int o = 16; o; o >>= 1) {
        s  += __shfl_xor_sync(0xffffffffu, s, o);
        s2 += __shfl_xor_sync(0xffffffffu, s2, o);
    }
    if ((t & 31) == 0) { sh1[t >> 5] = s; sh2[t >> 5] = s2; }
    __syncthreads();
    s = sh1[t & 7]; s2 = sh2[t & 7];
#pragma unroll
    for (int o = 4; o; o >>= 1) {
        s  += __shfl_xor_sync(0xffffffffu, s, o);
        s2 += __shfl_xor_sync(0xffffffffu, s2, o);
    }
    float mu   = s * (1.0f / kD);
    float var  = fmaxf(s2 * (1.0f / kD) - mu * mu, 0.f);
    float rstd = rsqrtf(var + 1e-5f);
    __half* orow = out + (size_t)row * kD;
#pragma unroll
    for (int i = 0; i < 3; i++) {
        int c = t + i * 256;
        orow[c] = __float2half_rn((v[i] - mu) * rstd * w[c] + b[c]);
    }
}

// ------- FP16 GEMM (NT): C[M,N] = A[M,K] @ Bt[N,K]^T + bias (+gelu)(+res) ----
__global__ __launch_bounds__(256) void gemm_f16_nt(
        const __half* __restrict__ A, const __half* __restrict__ Bt,
        const float* __restrict__ bias, const float* __restrict__ res,
        void* __restrict__ Cout, int M, int N, int K, int act, int outHalf) {
    extern __shared__ __half hsm[];
    __half* AsBuf = hsm;
    __half* BsBuf = hsm + 3 * 128 * 40;
#define HAS(s, r, c) AsBuf[(s) * 5120 + (r) * 40 + (c)]
#define HBS(s, r, c) BsBuf[(s) * 5120 + (r) * 40 + (c)]
    int tid = threadIdx.x, lane = tid & 31, warp = tid >> 5;
    int g = lane >> 2, tg = lane & 3;
    int wm = (warp >> 1) * 32, wn = (warp & 1) * 64;
    int row0 = blockIdx.y * 128, col0 = blockIdx.x * 128;
    int ra = tid >> 1, cha = (tid & 1) * 16;
    const __half* Ap = A  + (size_t)(row0 + ra) * K + cha;
    const __half* Bp = Bt + (size_t)(col0 + ra) * K + cha;
    float acc[2][8][4] = {};

    auto issue = [&](int k0, int s) {
        if (k0 < K) {
            cp16(&HAS(s, ra, cha),     Ap + k0);
            cp16(&HAS(s, ra, cha + 8), Ap + k0 + 8);
            cp16(&HBS(s, ra, cha),     Bp + k0);
            cp16(&HBS(s, ra, cha + 8), Bp + k0 + 8);
        }
        cp_commit();
    };
    issue(0, 0);
    issue(32, 1);
    int s = 0;
    for (int k0 = 0; k0 < K; k0 += 32) {
        cp_wait1();
        __syncthreads();
        int s2n = s + 2 >= 3 ? s - 1 : s + 2;
        issue(k0 + 64, s2n);
#pragma unroll
        for (int k16 = 0; k16 < 32; k16 += 16) {
            uint32_t af[2][4], bf[8][2];
#pragma unroll
            for (int mi = 0; mi < 2; mi++) {
                int r = wm + mi * 16 + g;
                af[mi][0] = *(const uint32_t*)&HAS(s, r,     k16 + 2 * tg);
                af[mi][1] = *(const uint32_t*)&HAS(s, r + 8, k16 + 2 * tg);
                af[mi][2] = *(const uint32_t*)&HAS(s, r,     k16 + 2 * tg + 8);
                af[mi][3] = *(const uint32_t*)&HAS(s, r + 8, k16 + 2 * tg + 8);
            }
#pragma unroll
            for (int nj = 0; nj < 8; nj++) {
                int n = wn + nj * 8 + g;
                bf[nj][0] = *(const uint32_t*)&HBS(s, n, k16 + 2 * tg);
                bf[nj][1] = *(const uint32_t*)&HBS(s, n, k16 + 2 * tg + 8);
            }
#pragma unroll
            for (int mi = 0; mi < 2; mi++)
#pragma unroll
                for (int nj = 0; nj < 8; nj++)
                    mma16h(acc[mi][nj], af[mi], bf[nj]);
        }
        s = s + 1 >= 3 ? 0 : s + 1;
    }
#undef HAS
#undef HBS
#pragma unroll
    for (int mi = 0; mi < 2; mi++) {
#pragma unroll
        for (int nj = 0; nj < 8; nj++) {
            int r0 = row0 + wm + mi * 16 + g;
            int c = col0 + wn + nj * 8 + tg * 2;
            float b0 = bias[c], b1 = bias[c + 1];
            float o00 = acc[mi][nj][0] + b0, o01 = acc[mi][nj][1] + b1;
            float o10 = acc[mi][nj][2] + b0, o11 = acc[mi][nj][3] + b1;
            if (act) {
                o00 = gelu_exact(o00); o01 = gelu_exact(o01);
                o10 = gelu_exact(o10); o11 = gelu_exact(o11);
            }
            if (res) {
                o00 += res[(size_t)r0 * N + c];       o01 += res[(size_t)r0 * N + c + 1];
                o10 += res[(size_t)(r0 + 8) * N + c]; o11 += res[(size_t)(r0 + 8) * N + c + 1];
            }
            if (outHalf) {
                __half* C = (__half*)Cout;
                *(__half2*)&C[(size_t)r0 * N + c]       = __floats2half2_rn(o00, o01);
                *(__half2*)&C[(size_t)(r0 + 8) * N + c] = __floats2half2_rn(o10, o11);
            } else {
                float* C = (float*)Cout;
                *(float2*)&C[(size_t)r0 * N + c]       = make_float2(o00, o01);
                *(float2*)&C[(size_t)(r0 + 8) * N + c] = make_float2(o10, o11);
            }
        }
    }
}

// ---- batched NT fp16 GEMM, K=64 fixed: C[bh] = scale * A[bh] @ B[bh]^T ------
// Serves score (A=Q,B=K, rowStr=kQD) and gmat (A=B=gw, rowStr=64).
// Per-bh base = ptr + (bh/kH)*batchStr + (bh%kH)*headStr.
__global__ __launch_bounds__(256) void nt64_f16(
        const __half* __restrict__ Abase, const __half* __restrict__ Bbase,
        size_t batchStr, size_t headStr, int rowStr, float scale,
        __half* __restrict__ C) {
    __shared__ __align__(16) __half As[128][72];
    __shared__ __align__(16) __half Bs[128][72];
    int bh = blockIdx.z, b = bh / kH, h = bh % kH;
    const __half* Ab = Abase + (size_t)b * batchStr + (size_t)h * headStr;
    const __half* Bb = Bbase + (size_t)b * batchStr + (size_t)h * headStr;
    int tid = threadIdx.x, lane = tid & 31, warp = tid >> 5;
    int g = lane >> 2, tg = lane & 3;
    int wm = (warp >> 1) * 32, wn = (warp & 1) * 64;
    int n0 = blockIdx.y * 128, m0 = blockIdx.x * 128;
    for (int i = tid; i < 1024; i += 256) {
        int r = i >> 3, ch = (i & 7) * 8;
        cp16(&As[r][ch], Ab + (size_t)(n0 + r) * rowStr + ch);
        cp16(&Bs[r][ch], Bb + (size_t)(m0 + r) * rowStr + ch);
    }
    cp_commit();
    cp_wait0();
    __syncthreads();
    float acc[2][8][4] = {};
#pragma unroll
    for (int k16 = 0; k16 < 64; k16 += 16) {
        uint32_t af[2][4], bf[8][2];
#pragma unroll
        for (int mi = 0; mi < 2; mi++) {
            int r = wm + mi * 16 + g;
            af[mi][0] = *(const uint32_t*)&As[r][k16 + 2 * tg];
            af[mi][1] = *(const uint32_t*)&As[r + 8][k16 + 2 * tg];
            af[mi][2] = *(const uint32_t*)&As[r][k16 + 2 * tg + 8];
            af[mi][3] = *(const uint32_t*)&As[r + 8][k16 + 2 * tg + 8];
        }
#pragma unroll
        for (int nj = 0; nj < 8; nj++) {
            int n = wn + nj * 8 + g;
            bf[nj][0] = *(const uint32_t*)&Bs[n][k16 + 2 * tg];
            bf[nj][1] = *(const uint32_t*)&Bs[n][k16 + 2 * tg + 8];
        }
#pragma unroll
        for (int mi = 0; mi < 2; mi++)
#pragma unroll
            for (int nj = 0; nj < 8; nj++)
                mma16h(acc[mi][nj], af[mi], bf[nj]);
    }
    __half* Cb = C + (size_t)bh * kN * kN;
#pragma unroll
    for (int mi = 0; mi < 2; mi++) {
#pragma unroll
        for (int nj = 0; nj < 8; nj++) {
            int r0 = n0 + wm + mi * 16 + g;
            int c = m0 + wn + nj * 8 + tg * 2;
            *(__half2*)&Cb[(size_t)r0 * kN + c] =
                __floats2half2_rn(acc[mi][nj][0] * scale, acc[mi][nj][1] * scale);
            *(__half2*)&Cb[(size_t)(r0 + 8) * kN + c] =
                __floats2half2_rn(acc[mi][nj][2] * scale, acc[mi][nj][3] * scale);
        }
    }
}

// ------- per-row: P = softmax(S*G); A = (1-a)P + a*G  (all fp16 storage) -----
__global__ __launch_bounds__(256) void rowmix_kernel(const float* __restrict__ alpha,
                                                     __half* __restrict__ S,
                                                     const __half* __restrict__ G) {
    __shared__ float sh1[8];
    int gr = blockIdx.x;                 // bh*N + n
    int h = (gr >> 10) % kH;
    size_t off = (size_t)gr * kN;
    int t = threadIdx.x;
    float a = 1.f / (1.f + __expf(-alpha[h]));
    __half2* Sh = (__half2*)(S + off);
    const __half2* Gh = (const __half2*)(G + off);
    __half2 p0 = Sh[t * 2], p1 = Sh[t * 2 + 1];
    __half2 q0 = Gh[t * 2], q1 = Gh[t * 2 + 1];
    float2 f0 = __half22float2(p0), f1 = __half22float2(p1);
    float2 g0 = __half22float2(q0), g1 = __half22float2(q1);
    float gv[4] = { g0.x, g0.y, g1.x, g1.y };
    float tv[4] = { f0.x * gv[0], f0.y * gv[1], f1.x * gv[2], f1.y * gv[3] };
    float mx = fmaxf(fmaxf(tv[0], tv[1]), fmaxf(tv[2], tv[3]));
    for (int o = 16; o; o >>= 1) mx = fmaxf(mx, __shfl_xor_sync(0xffffffffu, mx, o));
    if ((t & 31) == 0) sh1[t >> 5] = mx;
    __syncthreads();
    mx = sh1[t & 7];
    for (int o = 4; o; o >>= 1) mx = fmaxf(mx, __shfl_xor_sync(0xffffffffu, mx, o));
    __syncthreads();
    float e[4], sum = 0.f;
#pragma unroll
    for (int i = 0; i < 4; i++) { e[i] = __expf(tv[i] - mx); sum += e[i]; }
    for (int o = 16; o; o >>= 1) sum += __shfl_xor_sync(0xffffffffu, sum, o);
    if ((t & 31) == 0) sh1[t >> 5] = sum;
    __syncthreads();
    sum = sh1[t & 7];
    for (int o = 4; o; o >>= 1) sum += __shfl_xor_sync(0xffffffffu, sum, o);
    float isum = (1.f - a) / sum;
    Sh[t * 2]     = __floats2half2_rn(e[0] * isum + a * gv[0], e[1] * isum + a * gv[1]);
    Sh[t * 2 + 1] = __floats2half2_rn(e[2] * isum + a * gv[2], e[3] * isum + a * gv[3]);
}

// ------- column sums over n (axis=2), fp16 A, stores 1/(sum+1e-8) -------
__global__ __launch_bounds__(256) void colsum_kernel(const __half* __restrict__ Sa,
                                                     float* __restrict__ inv) {
    int idx = blockIdx.x * 256 + threadIdx.x;   // bh*N + m
    int bh = idx >> 10, m = idx & 1023;
    const __half* p = Sa + (size_t)bh * kN * kN + m;
    float s0 = 0.f, s1 = 0.f, s2 = 0.f, s3 = 0.f;
    float s4 = 0.f, s5 = 0.f, s6 = 0.f, s7 = 0.f;
#pragma unroll 4
    for (int n = 0; n < kN; n += 8) {
        s0 += __half2float(p[(size_t)(n + 0) * kN]);
        s1 += __half2float(p[(size_t)(n + 1) * kN]);
        s2 += __half2float(p[(size_t)(n + 2) * kN]);
        s3 += __half2float(p[(size_t)(n + 3) * kN]);
        s4 += __half2float(p[(size_t)(n + 4) * kN]);
        s5 += __half2float(p[(size_t)(n + 5) * kN]);
        s6 += __half2float(p[(size_t)(n + 6) * kN]);
        s7 += __half2float(p[(size_t)(n + 7) * kN]);
    }
    float s = ((s0 + s1) + (s2 + s3)) + ((s4 + s5) + (s6 + s7));
    inv[idx] = 1.f / (s + 1e-8f);
}

// ------- vs[bh][d][k] = V[b,k,h,d] * inv[bh,k]   (fp16 in, transposed fp16) --
__global__ __launch_bounds__(256) void vscale_t_kernel(const __half* __restrict__ qkvh,
                                                       const float* __restrict__ inv,
                                                       __half* __restrict__ vs) {
    __shared__ __half tile[64][72];
    int bh = blockIdx.y, k0 = blockIdx.x * 64;
    int b = bh / kH, h = bh % kH;
    int t = threadIdx.x;
    for (int i = t; i < 64 * 16; i += 256) {
        int kk = i >> 4, d4 = (i & 15) * 4;
        float iv = inv[bh * kN + k0 + kk];
        const __half* src = qkvh + (size_t)(b * kN + k0 + kk) * kQD + 2 * kD + h * kHD + d4;
        __half2 h01 = *(const __half2*)(src);
        __half2 h23 = *(const __half2*)(src + 2);
        float2 f01 = __half22float2(h01), f23 = __half22float2(h23);
        tile[d4 + 0][kk] = __float2half_rn(f01.x * iv);
        tile[d4 + 1][kk] = __float2half_rn(f01.y * iv);
        tile[d4 + 2][kk] = __float2half_rn(f23.x * iv);
        tile[d4 + 3][kk] = __float2half_rn(f23.y * iv);
    }
    __syncthreads();
    for (int i = t; i < 64 * 8; i += 256) {
        int d = i >> 3, ch = (i & 7) * 8;
        *(uint4*)(vs + ((size_t)bh * kHD + d) * kN + k0 + ch) = *(uint4*)&tile[d][ch];
    }
}

// ------- out = A @ Vs (fp16 m16n8k16, fp32 accum), ctx fp16 out ---------------
__global__ __launch_bounds__(256) void av_f16(const __half* __restrict__ Sa,
                                              const __half* __restrict__ vs,
                                              __half* __restrict__ ctx) {
    __shared__ __align__(16) __half As[3][128][24];
    __shared__ __align__(16) __half Bs[3][64][24];
    int bh = blockIdx.z, b = bh / kH, h = bh % kH;
    const __half* Ab = Sa + (size_t)bh * kN * kN;
    const __half* vb = vs + (size_t)bh * kHD * kN;
    int tid = threadIdx.x, lane = tid & 31, warp = tid >> 5;
    int g = lane >> 2, tg = lane & 3;
    int wm = (warp >> 1) * 32, wn = (warp & 1) * 32;
    int row0 = blockIdx.y * 128;
    int ra = tid >> 1, cha = (tid & 1) * 8;
    int db = (tid & 127) >> 1, chb = (tid & 1) * 8;
    const __half* Ap = Ab + (size_t)(row0 + ra) * kN + cha;
    const __half* Vp = vb + (size_t)db * kN + chb;
    float acc[2][4][4] = {};
    auto issue = [&](int k0, int s) {
        if (k0 < kN) {
            cp16(&As[s][ra][cha], Ap + k0);
            if (tid < 128) cp16(&Bs[s][db][chb], Vp + k0);
        }
        cp_commit();
    };
    issue(0, 0);
    issue(16, 1);
    int s = 0;
    for (int k0 = 0; k0 < kN; k0 += 16) {
        cp_wait1();
        __syncthreads();
        int s2n = s + 2 >= 3 ? s - 1 : s + 2;
        issue(k0 + 32, s2n);
        uint32_t af[2][4], bf[4][2];
#pragma unroll
        for (int mi = 0; mi < 2; mi++) {
            int r = wm + mi * 16 + g;
            af[mi][0] = *(const uint32_t*)&As[s][r][2 * tg];
            af[mi][1] = *(const uint32_t*)&As[s][r + 8][2 * tg];
            af[mi][2] = *(const uint32_t*)&As[s][r][2 * tg + 8];
            af[mi][3] = *(const uint32_t*)&As[s][r + 8][2 * tg + 8];
        }
#pragma unroll
        for (int nj = 0; nj < 4; nj++) {
            int n = wn + nj * 8 + g;
            bf[nj][0] = *(const uint32_t*)&Bs[s][n][2 * tg];
            bf[nj][1] = *(const uint32_t*)&Bs[s][n][2 * tg + 8];
        }
#pragma unroll
        for (int mi = 0; mi < 2; mi++)
#pragma unroll
            for (int nj = 0; nj < 4; nj++)
                mma16h(acc[mi][nj], af[mi], bf[nj]);
        s = s + 1 >= 3 ? 0 : s + 1;
    }
#pragma unroll
    for (int mi = 0; mi < 2; mi++) {
#pragma unroll
        for (int nj = 0; nj < 4; nj++) {
            int tok0 = b * kN + row0 + wm + mi * 16 + g;
            int c = h * kHD + wn + nj * 8 + tg * 2;
            *(__half2*)&ctx[(size_t)tok0 * kD + c] =
                __floats2half2_rn(acc[mi][nj][0], acc[mi][nj][1]);
            *(__half2*)&ctx[(size_t)(tok0 + 8) * kD + c] =
                __floats2half2_rn(acc[mi][nj][2], acc[mi][nj][3]);
        }
    }
}

// ---- group weights: gw = softmax(gelu(V @ gp^T)), fp16 in/out, pad to 64 ----
__global__ __launch_bounds__(256) void gw_kernel(const __half* __restrict__ qkvh,
                                                 const float* __restrict__ gp_w,
                                                 __half* __restrict__ gw) {
    __shared__ __align__(16) float gps[kGP][68];
    __shared__ __align__(16) float Vs[64][68];
    int bh = blockIdx.y;
    int b = bh / kH, h = bh % kH;
    int n0 = blockIdx.x * 64;
    int tid = threadIdx.x;
    const float* gph = gp_w + (size_t)h * kGP * kHD;
    for (int i = tid; i < kGP * 16; i += 256) {
        int r = i >> 4, c4 = (i & 15) * 4;
        *(float4*)&gps[r][c4] = *(const float4*)(gph + r * kHD + c4);
    }
    const __half* vb = qkvh + (size_t)(b * kN + n0) * kQD + 2 * kD + h * kHD;
    for (int i = tid; i < 64 * 16; i += 256) {
        int r = i >> 4, c4 = (i & 15) * 4;
        __half2 h01 = *(const __half2*)(vb + (size_t)r * kQD + c4);
        __half2 h23 = *(const __half2*)(vb + (size_t)r * kQD + c4 + 2);
        float2 f01 = __half22float2(h01), f23 = __half22float2(h23);
        Vs[r][c4 + 0] = f01.x; Vs[r][c4 + 1] = f01.y;
        Vs[r][c4 + 2] = f23.x; Vs[r][c4 + 3] = f23.y;
    }
    __syncthreads();
    int r = tid >> 2;
    int c0 = tid & 3;
    float val[13];
    float mx = -1e30f;
#pragma unroll
    for (int j = 0; j < 13; j++) {
        int c = c0 + 4 * j;
        float acc = 0.f;
        if (c < kGP) {
#pragma unroll
            for (int d = 0; d < kHD; d += 4) {
                float4 vv = *(const float4*)&Vs[r][d];
                float4 gg = *(const float4*)&gps[c][d];
                acc += vv.x * gg.x + vv.y * gg.y + vv.z * gg.z + vv.w * gg.w;
            }
            acc = gelu_exact(acc);
            mx = fmaxf(mx, acc);
        }
        val[j] = acc;
    }
    mx = fmaxf(mx, __shfl_xor_sync(0xffffffffu, mx, 1));
    mx = fmaxf(mx, __shfl_xor_sync(0xffffffffu, mx, 2));
    float sum = 0.f;
#pragma unroll
    for (int j = 0; j < 13; j++) {
        int c = c0 + 4 * j;
        val[j] = (c < kGP) ? __expf(val[j] - mx) : 0.f;
        sum += val[j];
    }
    sum += __shfl_xor_sync(0xffffffffu, sum, 1);
    sum += __shfl_xor_sync(0xffffffffu, sum, 2);
    float is = 1.f / sum;
    __half* grow = gw + (size_t)(bh * kN + n0 + r) * 64;
#pragma unroll
    for (int j = 0; j < 16; j++) {
        int c = c0 + 4 * j;
        if (c < 64)
            grow[c] = __float2half_rn((j < 13 && c < kGP) ? val[j] * is : 0.f);
    }
}

// ---------------- launch ----------------
extern "C" void kernel_launch(void* const* d_in, const int* in_sizes, int n_in,
                              void* d_out, int out_size) {
    const float* x      = (const float*)d_in[0];
    const float* ln1_w  = (const float*)d_in[1];
    const float* ln1_b  = (const float*)d_in[2];
    const float* qkv_w  = (const float*)d_in[3];
    const float* qkv_b  = (const float*)d_in[4];
    const float* proj_w = (const float*)d_in[5];
    const float* proj_b = (const float*)d_in[6];
    const float* gp_w   = (const float*)d_in[7];
    const float* alpha  = (const float*)d_in[8];
    const float* ln2_w  = (const float*)d_in[9];
    const float* ln2_b  = (const float*)d_in[10];
    const float* ff1_w  = (const float*)d_in[11];
    const float* ff1_b  = (const float*)d_in[12];
    const float* ff2_w  = (const float*)d_in[13];
    const float* ff2_b  = (const float*)d_in[14];
    float* out = (float*)d_out;

    float *inv, *y;
    __half *xn, *qkvh, *S, *G, *gw, *vs, *ctx, *yn, *hdn;
    __half *qkvwt, *projwt, *ff1wt, *ff2wt;
    cudaGetSymbolAddress((void**)&xn,   g_xn);
    cudaGetSymbolAddress((void**)&qkvh, g_qkvh);
    cudaGetSymbolAddress((void**)&S,    g_S);
    cudaGetSymbolAddress((void**)&G,    g_G);
    cudaGetSymbolAddress((void**)&gw,   g_gw);
    cudaGetSymbolAddress((void**)&inv,  g_inv);
    cudaGetSymbolAddress((void**)&vs,   g_vs);
    cudaGetSymbolAddress((void**)&ctx,  g_ctx);
    cudaGetSymbolAddress((void**)&y,    g_y);
    cudaGetSymbolAddress((void**)&yn,   g_yn);
    cudaGetSymbolAddress((void**)&hdn,  g_hdn);
    cudaGetSymbolAddress((void**)&qkvwt,  g_qkvwt);
    cudaGetSymbolAddress((void**)&projwt, g_projwt);
    cudaGetSymbolAddress((void**)&ff1wt,  g_ff1wt);
    cudaGetSymbolAddress((void**)&ff2wt,  g_ff2wt);

    cudaFuncSetAttribute(gemm_f16_nt,
                         cudaFuncAttributeMaxDynamicSharedMemorySize, kGemmSmemH);

    // weight transposes (fp32 -> fp16, [K][N] -> [N][K])
    wt_kernel<<<dim3(kD / 32, kQD / 32), 256>>>(qkv_w, qkvwt, kD, kQD);
    wt_kernel<<<dim3(kD / 32, kD / 32), 256>>>(proj_w, projwt, kD, kD);
    wt_kernel<<<dim3(kD / 32, kMLP / 32), 256>>>(ff1_w, ff1wt, kD, kMLP);
    wt_kernel<<<dim3(kMLP / 32, kD / 32), 256>>>(ff2_w, ff2wt, kMLP, kD);

    // attention branch
    ln_kernel<<<kT, 256>>>(x, ln1_w, ln1_b, xn);
    gemm_f16_nt<<<dim3(kQD / 128, kT / 128), 256, kGemmSmemH>>>(
        xn, qkvwt, qkv_b, nullptr, qkvh, kT, kQD, kD, 0, 1);
    // scores: A=Q (offset 0), B=K (offset kD), rowStr=kQD, scale=1/8
    nt64_f16<<<dim3(8, 8, kBH), 256>>>(qkvh, qkvh + kD,
                                       (size_t)kN * kQD, (size_t)kHD, kQD, 0.125f, S);
    gw_kernel<<<dim3(kN / 64, kBH), 256>>>(qkvh, gp_w, gw);
    // G = gw @ gw^T: rowStr=64, per-bh stride kN*64
    nt64_f16<<<dim3(8, 8, kBH), 256>>>(gw, gw,
                                       (size_t)kH * kN * 64, (size_t)kN * 64, 64, 1.0f, G);
    rowmix_kernel<<<kBH * kN, 256>>>(alpha, S, G);
    colsum_kernel<<<kBH * kN / 256, 256>>>(S, inv);
    vscale_t_kernel<<<dim3(kN / 64, kBH), 256>>>(qkvh, inv, vs);
    av_f16<<<dim3(1, 8, kBH), 256>>>(S, vs, ctx);
    gemm_f16_nt<<<dim3(kD / 128, kT / 128), 256, kGemmSmemH>>>(
        ctx, projwt, proj_b, x, y, kT, kD, kD, 0, 0);
    // FFN branch
    ln_kernel<<<kT, 256>>>(y, ln2_w, ln2_b, yn);
    gemm_f16_nt<<<dim3(kMLP / 128, kT / 128), 256, kGemmSmemH>>>(
        yn, ff1wt, ff1_b, nullptr, hdn, kT, kMLP, kD, 1, 1);
    gemm_f16_nt<<<dim3(kD / 128, kT / 128), 256, kGemmSmemH>>>(
        hdn, ff2wt, ff2_b, y, out, kT, kD, kMLP, 0, 0);
}

// round 15
// speedup vs baseline: 1.7434x; 1.0659x over previous
#include <cuda_runtime.h>
#include <cuda_fp16.h>
#include <math.h>
#include <stdint.h>

// ---------------- problem constants ----------------
namespace {
constexpr int kB  = 4;
constexpr int kN  = 1024;
constexpr int kD  = 768;
constexpr int kH  = 12;
constexpr int kHD = 64;
constexpr int kGP = 49;
constexpr int kMLP = 3072;
constexpr int kT  = kB * kN;     // 4096 tokens
constexpr int kBH = kB * kH;     // 48 batched heads
constexpr int kQD = 3 * kD;      // 2304
constexpr int kGemmSmemH = 3 * (128 * 40 + 128 * 40) * 2;
}

// ---------------- scratch (device globals: no allocation allowed) ----------------
__device__ __half g_xn  [kT * kD];
__device__ __half g_qkvh[kT * kQD];
__device__ __half g_S   [(size_t)kBH * kN * kN];
__device__ __half g_G   [(size_t)kBH * kN * kN];
__device__ __half g_gw  [kBH * kN * 64];
__device__ float  g_inv [kBH * kN];
__device__ __half g_vs  [(size_t)kBH * kHD * kN];
__device__ __half g_ctx [kT * kD];
__device__ float  g_y   [kT * kD];
__device__ __half g_yn  [kT * kD];
__device__ __half g_hdn [kT * kMLP];
__device__ __half g_qkvwt[kQD * kD];
__device__ __half g_projwt[kD * kD];
__device__ __half g_ff1wt [kMLP * kD];
__device__ __half g_ff2wt [kD * kMLP];

__device__ __forceinline__ float gelu_exact(float x) {
    return 0.5f * x * (1.0f + erff(x * 0.70710678118654752440f));
}

__device__ __forceinline__ void cp16(void* dst_smem, const void* src_gmem) {
    uint32_t d = (uint32_t)__cvta_generic_to_shared(dst_smem);
    asm volatile("cp.async.cg.shared.global [%0], [%1], 16;" :: "r"(d), "l"(src_gmem));
}
__device__ __forceinline__ void cp_commit() {
    asm volatile("cp.async.commit_group;");
}
__device__ __forceinline__ void cp_wait0() {
    asm volatile("cp.async.wait_group 0;");
}
__device__ __forceinline__ void cp_wait1() {
    asm volatile("cp.async.wait_group 1;");
}

// ldmatrix x4 (non-trans): r0..r3 = the four 8x8 b16 tiles whose row
// addresses are supplied by lanes 0-7 / 8-15 / 16-23 / 24-31.
__device__ __forceinline__ void ldsm_x4(uint32_t* r, uint32_t smem_addr) {
    asm volatile("ldmatrix.sync.aligned.m8n8.x4.shared.b16 {%0,%1,%2,%3}, [%4];"
                 : "=r"(r[0]), "=r"(r[1]), "=r"(r[2]), "=r"(r[3])
                 : "r"(smem_addr));
}

// D += A(m16k16,row,f16) * B(k16n8,col,f16), fp32 accum
__device__ __forceinline__ void mma16h(float* c, const uint32_t* a, const uint32_t* b) {
    asm volatile("mma.sync.aligned.m16n8k16.row.col.f32.f16.f16.f32 "
                 "{%0,%1,%2,%3}, {%4,%5,%6,%7}, {%8,%9}, {%0,%1,%2,%3};"
                 : "+f"(c[0]), "+f"(c[1]), "+f"(c[2]), "+f"(c[3])
                 : "r"(a[0]), "r"(a[1]), "r"(a[2]), "r"(a[3]),
                   "r"(b[0]), "r"(b[1]));
}

// ------- weight transpose+convert: Wt[n][k] = (half)W[k][n] ------------------
__global__ __launch_bounds__(256) void wt_kernel(const float* __restrict__ W,
                                                 __half* __restrict__ Wt,
                                                 int K, int N) {
    __shared__ float tile[32][33];
    int k0 = blockIdx.x * 32, n0 = blockIdx.y * 32;
    int t = threadIdx.x;
    int i = t & 31, j0 = t >> 5;
#pragma unroll
    for (int jj = 0; jj < 32; jj += 8)
        tile[j0 + jj][i] = W[(size_t)(k0 + j0 + jj) * N + n0 + i];
    __syncthreads();
#pragma unroll
    for (int jj = 0; jj < 32; jj += 8)
        Wt[(size_t)(n0 + j0 + jj) * K + k0 + i] = __float2half_rn(tile[i][j0 + jj]);
}

// ---------------- LayerNorm: fp32 in, fp16 out; one block per row -------------
__global__ __launch_bounds__(256) void ln_kernel(const float* __restrict__ x,
                                                 const float* __restrict__ w,
                                                 const float* __restrict__ b,
                                                 __half* __restrict__ out) {
    __shared__ float sh1[8], sh2[8];
    int row = blockIdx.x;
    int t = threadIdx.x;
    const float* xr = x + (size_t)row * kD;
    float v[3];
    float s = 0.f, s2 = 0.f;
#pragma unroll
    for (int i = 0; i < 3; i++) {
        v[i] = xr[t + i * 256];
        s  += v[i];
        s2 += v[i] * v[i];
    }
#pragma unroll
    for (int o = 16; o; o >>= 1) {
        s  += __shfl_xor_sync(0xffffffffu, s, o);
        s2 += __shfl_xor_sync(0xffffffffu, s2, o);
    }
    if ((t & 31) == 0) { sh1[t >> 5] = s; sh2[t >> 5] = s2; }
    __syncthreads();
    s = sh1[t & 7]; s2 = sh2[t & 7];
#pragma unroll
    for (int o = 4; o; o >>= 1) {
        s  += __shfl_xor_sync(0xffffffffu, s, o);
        s2 += __shfl_xor_sync(0xffffffffu, s2, o);
    }
    float mu   = s * (1.0f / kD);
    float var  = fmaxf(s2 * (1.0f / kD) - mu * mu, 0.f);
    float rstd = rsqrtf(var + 1e-5f);
    __half* orow = out + (size_t)row * kD;
#pragma unroll
    for (int i = 0; i < 3; i++) {
        int c = t + i * 256;
        orow[c] = __float2half_rn((v[i] - mu) * rstd * w[c] + b[c]);
    }
}

// ------- FP16 GEMM (NT): C[M,N] = A[M,K] @ Bt[N,K]^T + bias (+gelu)(+res) ----
// 128x128 block, 8 warps, K-step 32, 3-stage cp.async, ldmatrix fragments.
__global__ __launch_bounds__(256) void gemm_f16_nt(
        const __half* __restrict__ A, const __half* __restrict__ Bt,
        const float* __restrict__ bias, const float* __restrict__ res,
        void* __restrict__ Cout, int M, int N, int K, int act, int outHalf) {
    extern __shared__ __half hsm[];
    __half* AsBuf = hsm;
    __half* BsBuf = hsm + 3 * 128 * 40;
    uint32_t asBase = (uint32_t)__cvta_generic_to_shared(AsBuf);
    uint32_t bsBase = (uint32_t)__cvta_generic_to_shared(BsBuf);
#define HAS(s, r, c) AsBuf[(s) * 5120 + (r) * 40 + (c)]
#define HBS(s, r, c) BsBuf[(s) * 5120 + (r) * 40 + (c)]
    int tid = threadIdx.x, lane = tid & 31, warp = tid >> 5;
    int g = lane >> 2, tg = lane & 3;
    int lr = lane & 7, sel = lane >> 3;
    int wm = (warp >> 1) * 32, wn = (warp & 1) * 64;
    int row0 = blockIdx.y * 128, col0 = blockIdx.x * 128;
    int ra = tid >> 1, cha = (tid & 1) * 16;
    const __half* Ap = A  + (size_t)(row0 + ra) * K + cha;
    const __half* Bp = Bt + (size_t)(col0 + ra) * K + cha;
    float acc[2][8][4] = {};

    auto issue = [&](int k0, int s) {
        if (k0 < K) {
            cp16(&HAS(s, ra, cha),     Ap + k0);
            cp16(&HAS(s, ra, cha + 8), Ap + k0 + 8);
            cp16(&HBS(s, ra, cha),     Bp + k0);
            cp16(&HBS(s, ra, cha + 8), Bp + k0 + 8);
        }
        cp_commit();
    };
    issue(0, 0);
    issue(32, 1);
    int s = 0;
    for (int k0 = 0; k0 < K; k0 += 32) {
        cp_wait1();
        __syncthreads();
        int s2n = s + 2 >= 3 ? s - 1 : s + 2;
        issue(k0 + 64, s2n);
#pragma unroll
        for (int k16 = 0; k16 < 32; k16 += 16) {
            uint32_t af[2][4], bf[8][2];
#pragma unroll
            for (int mi = 0; mi < 2; mi++) {
                int r = wm + mi * 16 + lr + (sel & 1) * 8;
                int c = k16 + (sel >> 1) * 8;
                ldsm_x4(af[mi], asBase + (s * 5120 + r * 40 + c) * 2);
            }
#pragma unroll
            for (int njp = 0; njp < 4; njp++) {
                int n = wn + njp * 16 + lr + (sel >> 1) * 8;
                int c = k16 + (sel & 1) * 8;
                uint32_t tmp[4];
                ldsm_x4(tmp, bsBase + (s * 5120 + n * 40 + c) * 2);
                bf[njp * 2][0] = tmp[0];     bf[njp * 2][1] = tmp[1];
                bf[njp * 2 + 1][0] = tmp[2]; bf[njp * 2 + 1][1] = tmp[3];
            }
#pragma unroll
            for (int mi = 0; mi < 2; mi++)
#pragma unroll
                for (int nj = 0; nj < 8; nj++)
                    mma16h(acc[mi][nj], af[mi], bf[nj]);
        }
        s = s + 1 >= 3 ? 0 : s + 1;
    }
#undef HAS
#undef HBS
#pragma unroll
    for (int mi = 0; mi < 2; mi++) {
#pragma unroll
        for (int nj = 0; nj < 8; nj++) {
            int r0 = row0 + wm + mi * 16 + g;
            int c = col0 + wn + nj * 8 + tg * 2;
            float b0 = bias[c], b1 = bias[c + 1];
            float o00 = acc[mi][nj][0] + b0, o01 = acc[mi][nj][1] + b1;
            float o10 = acc[mi][nj][2] + b0, o11 = acc[mi][nj][3] + b1;
            if (act) {
                o00 = gelu_exact(o00); o01 = gelu_exact(o01);
                o10 = gelu_exact(o10); o11 = gelu_exact(o11);
            }
            if (res) {
                o00 += res[(size_t)r0 * N + c];       o01 += res[(size_t)r0 * N + c + 1];
                o10 += res[(size_t)(r0 + 8) * N + c]; o11 += res[(size_t)(r0 + 8) * N + c + 1];
            }
            if (outHalf) {
                __half* C = (__half*)Cout;
                *(__half2*)&C[(size_t)r0 * N + c]       = __floats2half2_rn(o00, o01);
                *(__half2*)&C[(size_t)(r0 + 8) * N + c] = __floats2half2_rn(o10, o11);
            } else {
                float* C = (float*)Cout;
                *(float2*)&C[(size_t)r0 * N + c]       = make_float2(o00, o01);
                *(float2*)&C[(size_t)(r0 + 8) * N + c] = make_float2(o10, o11);
            }
        }
    }
}

// ---- batched NT fp16 GEMM, K=64 fixed: C[bh] = scale * A[bh] @ B[bh]^T ------
__global__ __launch_bounds__(256) void nt64_f16(
        const __half* __restrict__ Abase, const __half* __restrict__ Bbase,
        size_t batchStr, size_t headStr, int rowStr, float scale,
        __half* __restrict__ C) {
    __shared__ __align__(16) __half As[128][72];
    __shared__ __align__(16) __half Bs[128][72];
    uint32_t asBase = (uint32_t)__cvta_generic_to_shared(&As[0][0]);
    uint32_t bsBase = (uint32_t)__cvta_generic_to_shared(&Bs[0][0]);
    int bh = blockIdx.z, b = bh / kH, h = bh % kH;
    const __half* Ab = Abase + (size_t)b * batchStr + (size_t)h * headStr;
    const __half* Bb = Bbase + (size_t)b * batchStr + (size_t)h * headStr;
    int tid = threadIdx.x, lane = tid & 31, warp = tid >> 5;
    int g = lane >> 2, tg = lane & 3;
    int lr = lane & 7, sel = lane >> 3;
    int wm = (warp >> 1) * 32, wn = (warp & 1) * 64;
    int n0 = blockIdx.y * 128, m0 = blockIdx.x * 128;
    for (int i = tid; i < 1024; i += 256) {
        int r = i >> 3, ch = (i & 7) * 8;
        cp16(&As[r][ch], Ab + (size_t)(n0 + r) * rowStr + ch);
        cp16(&Bs[r][ch], Bb + (size_t)(m0 + r) * rowStr + ch);
    }
    cp_commit();
    cp_wait0();
    __syncthreads();
    float acc[2][8][4] = {};
#pragma unroll
    for (int k16 = 0; k16 < 64; k16 += 16) {
        uint32_t af[2][4], bf[8][2];
#pragma unroll
        for (int mi = 0; mi < 2; mi++) {
            int r = wm + mi * 16 + lr + (sel & 1) * 8;
            int c = k16 + (sel >> 1) * 8;
            ldsm_x4(af[mi], asBase + (r * 72 + c) * 2);
        }
#pragma unroll
        for (int njp = 0; njp < 4; njp++) {
            int n = wn + njp * 16 + lr + (sel >> 1) * 8;
            int c = k16 + (sel & 1) * 8;
            uint32_t tmp[4];
            ldsm_x4(tmp, bsBase + (n * 72 + c) * 2);
            bf[njp * 2][0] = tmp[0];     bf[njp * 2][1] = tmp[1];
            bf[njp * 2 + 1][0] = tmp[2]; bf[njp * 2 + 1][1] = tmp[3];
        }
#pragma unroll
        for (int mi = 0; mi < 2; mi++)
#pragma unroll
            for (int nj = 0; nj < 8; nj++)
                mma16h(acc[mi][nj], af[mi], bf[nj]);
    }
    __half* Cb = C + (size_t)bh * kN * kN;
#pragma unroll
    for (int mi = 0; mi < 2; mi++) {
#pragma unroll
        for (int nj = 0; nj < 8; nj++) {
            int r0 = n0 + wm + mi * 16 + g;
            int c = m0 + wn + nj * 8 + tg * 2;
            *(__half2*)&Cb[(size_t)r0 * kN + c] =
                __floats2half2_rn(acc[mi][nj][0] * scale, acc[mi][nj][1] * scale);
            *(__half2*)&Cb[(size_t)(r0 + 8) * kN + c] =
                __floats2half2_rn(acc[mi][nj][2] * scale, acc[mi][nj][3] * scale);
        }
    }
}

// ------- per-row: P = softmax(S*G); A = (1-a)P + a*G  (all fp16 storage) -----
__global__ __launch_bounds__(256) void rowmix_kernel(const float* __restrict__ alpha,
                                                     __half* __restrict__ S,
                                                     const __half* __restrict__ G) {
    __shared__ float sh1[8];
    int gr = blockIdx.x;                 // bh*N + n
    int h = (gr >> 10) % kH;
    size_t off = (size_t)gr * kN;
    int t = threadIdx.x;
    float a = 1.f / (1.f + __expf(-alpha[h]));
    __half2* Sh = (__half2*)(S + off);
    const __half2* Gh = (const __half2*)(G + off);
    __half2 p0 = Sh[t * 2], p1 = Sh[t * 2 + 1];
    __half2 q0 = Gh[t * 2], q1 = Gh[t * 2 + 1];
    float2 f0 = __half22float2(p0), f1 = __half22float2(p1);
    float2 g0 = __half22float2(q0), g1 = __half22float2(q1);
    float gv[4] = { g0.x, g0.y, g1.x, g1.y };
    float tv[4] = { f0.x * gv[0], f0.y * gv[1], f1.x * gv[2], f1.y * gv[3] };
    float mx = fmaxf(fmaxf(tv[0], tv[1]), fmaxf(tv[2], tv[3]));
    for (int o = 16; o; o >>= 1) mx = fmaxf(mx, __shfl_xor_sync(0xffffffffu, mx, o));
    if ((t & 31) == 0) sh1[t >> 5] = mx;
    __syncthreads();
    mx = sh1[t & 7];
    for (int o = 4; o; o >>= 1) mx = fmaxf(mx, __shfl_xor_sync(0xffffffffu, mx, o));
    __syncthreads();
    float e[4], sum = 0.f;
#pragma unroll
    for (int i = 0; i < 4; i++) { e[i] = __expf(tv[i] - mx); sum += e[i]; }
    for (int o = 16; o; o >>= 1) sum += __shfl_xor_sync(0xffffffffu, sum, o);
    if ((t & 31) == 0) sh1[t >> 5] = sum;
    __syncthreads();
    sum = sh1[t & 7];
    for (int o = 4; o; o >>= 1) sum += __shfl_xor_sync(0xffffffffu, sum, o);
    float isum = (1.f - a) / sum;
    Sh[t * 2]     = __floats2half2_rn(e[0] * isum + a * gv[0], e[1] * isum + a * gv[1]);
    Sh[t * 2 + 1] = __floats2half2_rn(e[2] * isum + a * gv[2], e[3] * isum + a * gv[3]);
}

// ------- column sums over n (axis=2), fp16 A, stores 1/(sum+1e-8) -------
__global__ __launch_bounds__(256) void colsum_kernel(const __half* __restrict__ Sa,
                                                     float* __restrict__ inv) {
    int idx = blockIdx.x * 256 + threadIdx.x;   // bh*N + m
    int bh = idx >> 10, m = idx & 1023;
    const __half* p = Sa + (size_t)bh * kN * kN + m;
    float s0 = 0.f, s1 = 0.f, s2 = 0.f, s3 = 0.f;
    float s4 = 0.f, s5 = 0.f, s6 = 0.f, s7 = 0.f;
#pragma unroll 4
    for (int n = 0; n < kN; n += 8) {
        s0 += __half2float(p[(size_t)(n + 0) * kN]);
        s1 += __half2float(p[(size_t)(n + 1) * kN]);
        s2 += __half2float(p[(size_t)(n + 2) * kN]);
        s3 += __half2float(p[(size_t)(n + 3) * kN]);
        s4 += __half2float(p[(size_t)(n + 4) * kN]);
        s5 += __half2float(p[(size_t)(n + 5) * kN]);
        s6 += __half2float(p[(size_t)(n + 6) * kN]);
        s7 += __half2float(p[(size_t)(n + 7) * kN]);
    }
    float s = ((s0 + s1) + (s2 + s3)) + ((s4 + s5) + (s6 + s7));
    inv[idx] = 1.f / (s + 1e-8f);
}

// ------- vs[bh][d][k] = V[b,k,h,d] * inv[bh,k]   (fp16 in, transposed fp16) --
__global__ __launch_bounds__(256) void vscale_t_kernel(const __half* __restrict__ qkvh,
                                                       const float* __restrict__ inv,
                                                       __half* __restrict__ vs) {
    __shared__ __half tile[64][72];
    int bh = blockIdx.y, k0 = blockIdx.x * 64;
    int b = bh / kH, h = bh % kH;
    int t = threadIdx.x;
    for (int i = t; i < 64 * 16; i += 256) {
        int kk = i >> 4, d4 = (i & 15) * 4;
        float iv = inv[bh * kN + k0 + kk];
        const __half* src = qkvh + (size_t)(b * kN + k0 + kk) * kQD + 2 * kD + h * kHD + d4;
        __half2 h01 = *(const __half2*)(src);
        __half2 h23 = *(const __half2*)(src + 2);
        float2 f01 = __half22float2(h01), f23 = __half22float2(h23);
        tile[d4 + 0][kk] = __float2half_rn(f01.x * iv);
        tile[d4 + 1][kk] = __float2half_rn(f01.y * iv);
        tile[d4 + 2][kk] = __float2half_rn(f23.x * iv);
        tile[d4 + 3][kk] = __float2half_rn(f23.y * iv);
    }
    __syncthreads();
    for (int i = t; i < 64 * 8; i += 256) {
        int d = i >> 3, ch = (i & 7) * 8;
        *(uint4*)(vs + ((size_t)bh * kHD + d) * kN + k0 + ch) = *(uint4*)&tile[d][ch];
    }
}

// ------- out = A @ Vs (fp16 m16n8k16, fp32 accum), ldmatrix, ctx fp16 --------
__global__ __launch_bounds__(256) void av_f16(const __half* __restrict__ Sa,
                                              const __half* __restrict__ vs,
                                              __half* __restrict__ ctx) {
    __shared__ __align__(16) __half As[3][128][24];
    __shared__ __align__(16) __half Bs[3][64][24];
    uint32_t asBase = (uint32_t)__cvta_generic_to_shared(&As[0][0][0]);
    uint32_t bsBase = (uint32_t)__cvta_generic_to_shared(&Bs[0][0][0]);
    int bh = blockIdx.z, b = bh / kH, h = bh % kH;
    const __half* Ab = Sa + (size_t)bh * kN * kN;
    const __half* vb = vs + (size_t)bh * kHD * kN;
    int tid = threadIdx.x, lane = tid & 31, warp = tid >> 5;
    int g = lane >> 2, tg = lane & 3;
    int lr = lane & 7, sel = lane >> 3;
    int wm = (warp >> 1) * 32, wn = (warp & 1) * 32;
    int row0 = blockIdx.y * 128;
    int ra = tid >> 1, cha = (tid & 1) * 8;
    int db = (tid & 127) >> 1, chb = (tid & 1) * 8;
    const __half* Ap = Ab + (size_t)(row0 + ra) * kN + cha;
    const __half* Vp = vb + (size_t)db * kN + chb;
    float acc[2][4][4] = {};
    auto issue = [&](int k0, int s) {
        if (k0 < kN) {
            cp16(&As[s][ra][cha], Ap + k0);
            if (tid < 128) cp16(&Bs[s][db][chb], Vp + k0);
        }
        cp_commit();
    };
    issue(0, 0);
    issue(16, 1);
    int s = 0;
    for (int k0 = 0; k0 < kN; k0 += 16) {
        cp_wait1();
        __syncthreads();
        int s2n = s + 2 >= 3 ? s - 1 : s + 2;
        issue(k0 + 32, s2n);
        uint32_t af[2][4], bf[4][2];
#pragma unroll
        for (int mi = 0; mi < 2; mi++) {
            int r = wm + mi * 16 + lr + (sel & 1) * 8;
            int c = (sel >> 1) * 8;
            ldsm_x4(af[mi], asBase + (s * 128 * 24 + r * 24 + c) * 2);
        }
#pragma unroll
        for (int njp = 0; njp < 2; njp++) {
            int n = wn + njp * 16 + lr + (sel >> 1) * 8;
            int c = (sel & 1) * 8;
            uint32_t tmp[4];
            ldsm_x4(tmp, bsBase + (s * 64 * 24 + n * 24 + c) * 2);
            bf[njp * 2][0] = tmp[0];     bf[njp * 2][1] = tmp[1];
            bf[njp * 2 + 1][0] = tmp[2]; bf[njp * 2 + 1][1] = tmp[3];
        }
#pragma unroll
        for (int mi = 0; mi < 2; mi++)
#pragma unroll
            for (int nj = 0; nj < 4; nj++)
                mma16h(acc[mi][nj], af[mi], bf[nj]);
        s = s + 1 >= 3 ? 0 : s + 1;
    }
#pragma unroll
    for (int mi = 0; mi < 2; mi++) {
#pragma unroll
        for (int nj = 0; nj < 4; nj++) {
            int tok0 = b * kN + row0 + wm + mi * 16 + g;
            int c = h * kHD + wn + nj * 8 + tg * 2;
            *(__half2*)&ctx[(size_t)tok0 * kD + c] =
                __floats2half2_rn(acc[mi][nj][0], acc[mi][nj][1]);
            *(__half2*)&ctx[(size_t)(tok0 + 8) * kD + c] =
                __floats2half2_rn(acc[mi][nj][2], acc[mi][nj][3]);
        }
    }
}

// ---- group weights: gw = softmax(gelu(V @ gp^T)), fp16 in/out, pad to 64 ----
__global__ __launch_bounds__(256) void gw_kernel(const __half* __restrict__ qkvh,
                                                 const float* __restrict__ gp_w,
                                                 __half* __restrict__ gw) {
    __shared__ __align__(16) float gps[kGP][68];
    __shared__ __align__(16) float Vs[64][68];
    int bh = blockIdx.y;
    int b = bh / kH, h = bh % kH;
    int n0 = blockIdx.x * 64;
    int tid = threadIdx.x;
    const float* gph = gp_w + (size_t)h * kGP * kHD;
    for (int i = tid; i < kGP * 16; i += 256) {
        int r = i >> 4, c4 = (i & 15) * 4;
        *(float4*)&gps[r][c4] = *(const float4*)(gph + r * kHD + c4);
    }
    const __half* vb = qkvh + (size_t)(b * kN + n0) * kQD + 2 * kD + h * kHD;
    for (int i = tid; i < 64 * 16; i += 256) {
        int r = i >> 4, c4 = (i & 15) * 4;
        __half2 h01 = *(const __half2*)(vb + (size_t)r * kQD + c4);
        __half2 h23 = *(const __half2*)(vb + (size_t)r * kQD + c4 + 2);
        float2 f01 = __half22float2(h01), f23 = __half22float2(h23);
        Vs[r][c4 + 0] = f01.x; Vs[r][c4 + 1] = f01.y;
        Vs[r][c4 + 2] = f23.x; Vs[r][c4 + 3] = f23.y;
    }
    __syncthreads();
    int r = tid >> 2;
    int c0 = tid & 3;
    float val[13];
    float mx = -1e30f;
#pragma unroll
    for (int j = 0; j < 13; j++) {
        int c = c0 + 4 * j;
        float acc = 0.f;
        if (c < kGP) {
#pragma unroll
            for (int d = 0; d < kHD; d += 4) {
                float4 vv = *(const float4*)&Vs[r][d];
                float4 gg = *(const float4*)&gps[c][d];
                acc += vv.x * gg.x + vv.y * gg.y + vv.z * gg.z + vv.w * gg.w;
            }
            acc = gelu_exact(acc);
            mx = fmaxf(mx, acc);
        }
        val[j] = acc;
    }
    mx = fmaxf(mx, __shfl_xor_sync(0xffffffffu, mx, 1));
    mx = fmaxf(mx, __shfl_xor_sync(0xffffffffu, mx, 2));
    float sum = 0.f;
#pragma unroll
    for (int j = 0; j < 13; j++) {
        int c = c0 + 4 * j;
        val[j] = (c < kGP) ? __expf(val[j] - mx) : 0.f;
        sum += val[j];
    }
    sum += __shfl_xor_sync(0xffffffffu, sum, 1);
    sum += __shfl_xor_sync(0xffffffffu, sum, 2);
    float is = 1.f / sum;
    __half* grow = gw + (size_t)(bh * kN + n0 + r) * 64;
#pragma unroll
    for (int j = 0; j < 16; j++) {
        int c = c0 + 4 * j;
        if (c < 64)
            grow[c] = __float2half_rn((j < 13 && c < kGP) ? val[j] * is : 0.f);
    }
}

// ---------------- launch ----------------
extern "C" void kernel_launch(void* const* d_in, const int* in_sizes, int n_in,
                              void* d_out, int out_size) {
    const float* x      = (const float*)d_in[0];
    const float* ln1_w  = (const float*)d_in[1];
    const float* ln1_b  = (const float*)d_in[2];
    const float* qkv_w  = (const float*)d_in[3];
    const float* qkv_b  = (const float*)d_in[4];
    const float* proj_w = (const float*)d_in[5];
    const float* proj_b = (const float*)d_in[6];
    const float* gp_w   = (const float*)d_in[7];
    const float* alpha  = (const float*)d_in[8];
    const float* ln2_w  = (const float*)d_in[9];
    const float* ln2_b  = (const float*)d_in[10];
    const float* ff1_w  = (const float*)d_in[11];
    const float* ff1_b  = (const float*)d_in[12];
    const float* ff2_w  = (const float*)d_in[13];
    const float* ff2_b  = (const float*)d_in[14];
    float* out = (float*)d_out;

    float *inv, *y;
    __half *xn, *qkvh, *S, *G, *gw, *vs, *ctx, *yn, *hdn;
    __half *qkvwt, *projwt, *ff1wt, *ff2wt;
    cudaGetSymbolAddress((void**)&xn,   g_xn);
    cudaGetSymbolAddress((void**)&qkvh, g_qkvh);
    cudaGetSymbolAddress((void**)&S,    g_S);
    cudaGetSymbolAddress((void**)&G,    g_G);
    cudaGetSymbolAddress((void**)&gw,   g_gw);
    cudaGetSymbolAddress((void**)&inv,  g_inv);
    cudaGetSymbolAddress((void**)&vs,   g_vs);
    cudaGetSymbolAddress((void**)&ctx,  g_ctx);
    cudaGetSymbolAddress((void**)&y,    g_y);
    cudaGetSymbolAddress((void**)&yn,   g_yn);
    cudaGetSymbolAddress((void**)&hdn,  g_hdn);
    cudaGetSymbolAddress((void**)&qkvwt,  g_qkvwt);
    cudaGetSymbolAddress((void**)&projwt, g_projwt);
    cudaGetSymbolAddress((void**)&ff1wt,  g_ff1wt);
    cudaGetSymbolAddress((void**)&ff2wt,  g_ff2wt);

    cudaFuncSetAttribute(gemm_f16_nt,
                         cudaFuncAttributeMaxDynamicSharedMemorySize, kGemmSmemH);

    // weight transposes (fp32 -> fp16, [K][N] -> [N][K])
    wt_kernel<<<dim3(kD / 32, kQD / 32), 256>>>(qkv_w, qkvwt, kD, kQD);
    wt_kernel<<<dim3(kD / 32, kD / 32), 256>>>(proj_w, projwt, kD, kD);
    wt_kernel<<<dim3(kD / 32, kMLP / 32), 256>>>(ff1_w, ff1wt, kD, kMLP);
    wt_kernel<<<dim3(kMLP / 32, kD / 32), 256>>>(ff2_w, ff2wt, kMLP, kD);

    // attention branch
    ln_kernel<<<kT, 256>>>(x, ln1_w, ln1_b, xn);
    gemm_f16_nt<<<dim3(kQD / 128, kT / 128), 256, kGemmSmemH>>>(
        xn, qkvwt, qkv_b, nullptr, qkvh, kT, kQD, kD, 0, 1);
    nt64_f16<<<dim3(8, 8, kBH), 256>>>(qkvh, qkvh + kD,
                                       (size_t)kN * kQD, (size_t)kHD, kQD, 0.125f, S);
    gw_kernel<<<dim3(kN / 64, kBH), 256>>>(qkvh, gp_w, gw);
    nt64_f16<<<dim3(8, 8, kBH), 256>>>(gw, gw,
                                       (size_t)kH * kN * 64, (size_t)kN * 64, 64, 1.0f, G);
    rowmix_kernel<<<kBH * kN, 256>>>(alpha, S, G);
    colsum_kernel<<<kBH * kN / 256, 256>>>(S, inv);
    vscale_t_kernel<<<dim3(kN / 64, kBH), 256>>>(qkvh, inv, vs);
    av_f16<<<dim3(1, 8, kBH), 256>>>(S, vs, ctx);
    gemm_f16_nt<<<dim3(kD / 128, kT / 128), 256, kGemmSmemH>>>(
        ctx, projwt, proj_b, x, y, kT, kD, kD, 0, 0);
    // FFN branch
    ln_kernel<<<kT, 256>>>(y, ln2_w, ln2_b, yn);
    gemm_f16_nt<<<dim3(kMLP / 128, kT / 128), 256, kGemmSmemH>>>(
        yn, ff1wt, ff1_b, nullptr, hdn, kT, kMLP, kD, 1, 1);
    gemm_f16_nt<<<dim3(kD / 128, kT / 128), 256, kGemmSmemH>>>(
        hdn, ff2wt, ff2_b, y, out, kT, kD, kMLP, 0, 0);
}